// round 11
// baseline (speedup 1.0000x reference)
#include <cuda_runtime.h>
#include <cuda_fp16.h>
#include <cstdint>

#define BATCH 16384
#define NK 100        // TENSOR_DIM
#define D 200         // 2*TENSOR_DIM
#define H1 512        // EMBED_SIZE/2
#define EM 1024       // EMBED_SIZE
#define WD 300        // WORD_DIM

#define PREAL 20400   // real quadratic pair count
#define PLIN  20600   // + 200 linear (term2) pairs
#define PPAD  20608   // padded to 32 (20600 = cl_b pair, rest zero)
#define NGROUP 5152   // PPAD / 4
#define NC32 644      // PPAD / 32
#define NCC  322      // chunk pairs
#define SPB_CHUNK 7680   // 120 n-rows * 32 p * 2B (global layout)
#define SPC 6656         // 104 n-rows * 64B (compact smem chunk)

// ---------------- scratch (device globals; no allocation) ----------------
__device__ float g_catT[D * BATCH];               // cat transposed [i][b]
__device__ unsigned char g_SpB[NC32 * SPB_CHUNK]; // Sp fp16, swizzled [c][n][p]
__device__ int2  g_groups[NGROUP];                // (j, i0) per 4-pair group
__device__ uint16_t g_gpk[NGROUP];                // packed (i0<<8)|j
__device__ float g_pdWT[WD * NK];
__device__ float g_l1WT[104 * H1];                // [k][m], rows 100..103 zero
__device__ unsigned char g_l2Wh[EM * H1 * 2];     // l2_W fp16 [e][k]
__device__ float g_term1[BATCH * NK];             // term1+term2+cl_b (pre-lrelu)
__device__ uint32_t g_hu[BATCH * 256];            // h as packed half2 [b][256]

__device__ __forceinline__ float lrelu(float x) { return x >= 0.f ? x : 0.1f * x; }

__device__ __forceinline__ uint32_t smem_u32(const void* p) {
    return (uint32_t)__cvta_generic_to_shared(p);
}
__device__ __forceinline__ uint32_t f2tf32(float x) {
    uint32_t r; asm("cvt.rna.tf32.f32 %0, %1;" : "=r"(r) : "f"(x)); return r;
}
__device__ __forceinline__ uint32_t pack_h2(float lo, float hi) {
    __half2 h = __floats2half2_rn(lo, hi);
    return *(uint32_t*)&h;
}
#define CP_ASYNC16(dst, src) \
    asm volatile("cp.async.cg.shared.global [%0], [%1], 16;" :: "r"(dst), "l"(src) : "memory")
#define CP_COMMIT() asm volatile("cp.async.commit_group;" ::: "memory")

__device__ __forceinline__ void mma_tf32(float* d, const uint32_t* a,
                                         uint32_t b0, uint32_t b1) {
    asm volatile(
        "mma.sync.aligned.m16n8k8.row.col.f32.tf32.tf32.f32 "
        "{%0,%1,%2,%3}, {%4,%5,%6,%7}, {%8,%9}, {%0,%1,%2,%3};"
        : "+f"(d[0]), "+f"(d[1]), "+f"(d[2]), "+f"(d[3])
        : "r"(a[0]), "r"(a[1]), "r"(a[2]), "r"(a[3]), "r"(b0), "r"(b1));
}
__device__ __forceinline__ void mma_f16(float* d, const uint32_t* a,
                                        uint32_t b0, uint32_t b1) {
    asm volatile(
        "mma.sync.aligned.m16n8k16.row.col.f32.f16.f16.f32 "
        "{%0,%1,%2,%3}, {%4,%5,%6,%7}, {%8,%9}, {%0,%1,%2,%3};"
        : "+f"(d[0]), "+f"(d[1]), "+f"(d[2]), "+f"(d[3])
        : "r"(a[0]), "r"(a[1]), "r"(a[2]), "r"(a[3]), "r"(b0), "r"(b1));
}

// ---------------- prep: small transposes ----------------
__global__ void k_prep_small(const float* __restrict__ pd_W,
                             const float* __restrict__ l1_W) {
    int stride = gridDim.x * blockDim.x;
    int t0 = blockIdx.x * blockDim.x + threadIdx.x;
    for (int l = t0; l < WD * NK; l += stride) {
        int c = l / NK, k = l - c * NK;
        g_pdWT[l] = pd_W[k * WD + c];
    }
    for (int l = t0; l < NK * H1; l += stride) {
        int k = l / H1, m = l - k * H1;
        g_l1WT[l] = l1_W[m * NK + k];
    }
}

__global__ void k_prep_l2h(const float* __restrict__ l2_W) {
    int idx = blockIdx.x * 256 + threadIdx.x;       // e*512 + k
    ((__half*)g_l2Wh)[idx] = __float2half_rn(l2_W[idx]);
}

// ---------------- prep: pair-group table (int2 + packed u16) ----------------
__global__ void k_prep_groups() {
    int j = threadIdx.x;
    if (j < 200) {
        int q = j >> 2, r = j & 3;
        int S = 2 * q * (q - 1) + r * q;
        int gbase = 50 * j - S;
        int i0 = j & ~3;
        int ng = (200 - i0) >> 2;
        for (int g = 0; g < ng; ++g) {
            int ii = i0 + 4 * g;
            g_groups[gbase + g] = make_int2(j, ii);
            g_gpk[gbase + g] = (uint16_t)((ii << 8) | j);
        }
    }
    int idx = j - 200;
    if (idx >= 0 && idx < 50) {
        g_groups[5100 + idx] = make_int2(200, idx * 4);
        g_gpk[5100 + idx] = (uint16_t)(((idx * 4) << 8) | 200);
    }
    if (idx == 50) { g_groups[5150] = make_int2(200, 200);
                     g_gpk[5150] = (uint16_t)((200 << 8) | 200); }
    if (idx == 51) { g_groups[5151] = make_int2(200, 204);
                     g_gpk[5151] = (uint16_t)((204 << 8) | 200); }
}

// ---------------- prep: Sp fp16, [chunk][n(120)][32 p] with block swizzle ----
__global__ void __launch_bounds__(256) k_prep_spb(const float* __restrict__ T,
                                                  const float* __restrict__ clW,
                                                  const float* __restrict__ clb) {
    int c = blockIdx.x;
    unsigned char* base = g_SpB + (size_t)c * SPB_CHUNK;
    for (int e = threadIdx.x; e < 3840; e += 256) {
        int n = e >> 5, pl = e & 31;
        int p = c * 32 + pl;
        float v = 0.f;
        if (n < NK) {
            if (p < PREAL) {
                int2 gi = g_groups[p >> 2];
                int i = gi.y + (p & 3), j = gi.x;
                if (i > j)       v = T[(n * D + i) * D + j] + T[(n * D + j) * D + i];
                else if (i == j) v = T[(n * D + i) * D + i];
            } else if (p < PLIN) {
                v = clW[n * D + (p - PREAL)];
            } else if (p == PLIN) {
                v = clb[n];
            }
        }
        int w = pl >> 1;
        int sg = ((n >> 1) & 3) << 2;
        int off = n * 64 + ((w ^ sg) << 2) + (pl & 1) * 2;
        *(__half*)(base + off) = __float2half_rn(v);
    }
}

// ---------------- embedding gather + projdown + leaky ----------------
__global__ void __launch_bounds__(256) k_cat(const int* __restrict__ x,
                                             const float* __restrict__ embed_W,
                                             const float* __restrict__ pd_b) {
    __shared__ float e_s[16][WD + 4];
    __shared__ float o_s[NK][17];
    __shared__ int   xs[16];
    int g = blockIdx.x;
    int row0 = g * 16;
    int slot = row0 / BATCH;
    int bbase = row0 - slot * BATCH;
    int t = threadIdx.x;
    if (t < 16) xs[t] = x[(bbase + t) * 2 + slot];
    __syncthreads();
    for (int l = t; l < 16 * WD; l += 256) {
        int r = l / WD, c = l - r * WD;
        e_s[r][c] = embed_W[(size_t)xs[r] * WD + c];
    }
    __syncthreads();
    int k  = t & 127;
    int rt = t >> 7;
    if (k < NK) {
        float acc[8];
#pragma unroll
        for (int q = 0; q < 8; ++q) acc[q] = 0.f;
        for (int c4 = 0; c4 < WD; c4 += 4) {
            float w0 = g_pdWT[(c4 + 0) * NK + k];
            float w1 = g_pdWT[(c4 + 1) * NK + k];
            float w2 = g_pdWT[(c4 + 2) * NK + k];
            float w3 = g_pdWT[(c4 + 3) * NK + k];
#pragma unroll
            for (int q = 0; q < 8; ++q) {
                float4 e = *(const float4*)&e_s[rt + 2 * q][c4];
                acc[q] += e.x * w0 + e.y * w1 + e.z * w2 + e.w * w3;
            }
        }
        float bk = pd_b[k];
#pragma unroll
        for (int q = 0; q < 8; ++q)
            o_s[k][rt + 2 * q] = lrelu(acc[q] + bk);
    }
    __syncthreads();
    for (int l = t; l < NK * 16; l += 256) {
        int kk = l >> 4, col = l & 15;
        g_catT[(slot * NK + kk) * BATCH + bbase + col] = o_s[kk][col];
    }
}

// ---------------- main: term1(+term2+bias) via mma.sync fp16 ----------------
// CTA: 64 b x 104 n, 8 warps (k-split: warp-half wh handles chunk cc*2+wh),
// 2 CTAs/SM -> 4 warps/SMSP. One __syncthreads per 64-pair iteration.
// Final: reduce the two k-half accumulators through smem (reuses B buffer).
#define CAT_STRIDE 228                          // words
#define SP_OFF   58368                          // 64 * 228 * 4
#define GRP_OFF  (SP_OFF + 2 * 2 * SPC)         // 58368 + 26624 = 84992
#define SMEM_MAIN (GRP_OFF + NGROUP * 2)        // 95296
#define BLOAD2 832                              // 2 chunks * 416 x 16B

__global__ void __launch_bounds__(256, 2) k_main_mma() {
    extern __shared__ char smem[];
    float* cat = (float*)smem;
    uint16_t* grp = (uint16_t*)(smem + GRP_OFF);
    uint32_t sb = smem_u32(smem);
    int tid = threadIdx.x, lane = tid & 31, wid = tid >> 5;
    int b0 = blockIdx.x * 64;

    // prologue: kick off pair 0 load into slot 0
    {
        const char* src = (const char*)g_SpB;
        for (int i = tid; i < BLOAD2; i += 256) {
            int ch = i / 416, off = i - ch * 416;
            CP_ASYNC16(sb + SP_OFF + ch * SPC + off * 16,
                       src + (size_t)ch * SPB_CHUNK + off * 16);
        }
        CP_COMMIT();
    }
    for (int l = tid; l < NGROUP / 2; l += 256)
        ((uint32_t*)grp)[l] = ((const uint32_t*)g_gpk)[l];
    for (int l = tid; l < D * 64; l += 256) {
        int i = l >> 6, b = l & 63;
        cat[b * CAT_STRIDE + i] = g_catT[i * BATCH + b0 + b];
    }
    if (tid < 64) {   // ones column + zero pad (slots 200..207)
        float* r = cat + tid * CAT_STRIDE;
        r[200] = 1.f;
#pragma unroll
        for (int s = 201; s < 208; ++s) r[s] = 0.f;
    }

    int gid = lane >> 2;      // 0..7
    int tc  = lane & 3;       // 0..3
    int w4 = wid & 3;         // row group
    int wh = wid >> 2;        // k-half: which chunk of the pair
    int R0 = w4 * 16;
    int rA = R0 + gid;
    int oa = (tc & 1) * 2;    // i offset within group
    int gsel = tc >> 1;       // which of 2 sub-groups
    // B word offsets (conflict-free via block swizzle)
    int sgB = ((gid >> 1) & 3) << 2;
    int ob[2][2];
#pragma unroll
    for (int s = 0; s < 2; ++s) {
        ob[s][0] = gid * 16 + ((s * 8 + tc) ^ sgB);
        ob[s][1] = gid * 16 + ((s * 8 + tc + 4) ^ sgB);
    }

    float acc[13][4];
#pragma unroll
    for (int t = 0; t < 13; ++t)
#pragma unroll
        for (int q = 0; q < 4; ++q) acc[t][q] = 0.f;

    const float* r0 = cat + rA * CAT_STRIDE;
    const float* r1 = r0 + 8 * CAT_STRIDE;

    for (int cc = 0; cc < NCC; ++cc) {
        int slot = cc & 1;
        asm volatile("cp.async.wait_group 0;" ::: "memory");
        __syncthreads();   // pair cc visible; everyone done with other slot
        if (cc + 1 < NCC) {
            const char* src = (const char*)g_SpB + (size_t)(cc + 1) * 2 * SPB_CHUNK;
            uint32_t dst = sb + SP_OFF + (slot ^ 1) * 2 * SPC;
            for (int i = tid; i < BLOAD2; i += 256) {
                int ch = i / 416, off = i - ch * 416;
                CP_ASYNC16(dst + ch * SPC + off * 16,
                           src + (size_t)ch * SPB_CHUNK + off * 16);
            }
            CP_COMMIT();
        }

        // this warp's chunk of the pair
        int c = cc * 2 + wh;
        const uint32_t* spu =
            (const uint32_t*)(smem + SP_OFF + slot * 2 * SPC + wh * SPC);
        int gb = c * 8;
#pragma unroll
        for (int ks = 0; ks < 2; ++ks) {   // two k16 steps per chunk
            int ga  = grp[gb + ks * 4 + gsel];
            int gb_ = grp[gb + ks * 4 + 2 + gsel];
            int ja = ga & 255,  ia = ga >> 8;
            int jb = gb_ & 255, ib = gb_ >> 8;
            float  ja0 = r0[ja], ja1 = r1[ja];
            float  jb0 = r0[jb], jb1 = r1[jb];
            float2 ia0 = *(const float2*)&r0[ia + oa];
            float2 ia1 = *(const float2*)&r1[ia + oa];
            float2 ib0 = *(const float2*)&r0[ib + oa];
            float2 ib1 = *(const float2*)&r1[ib + oa];
            uint32_t afr[4];
            afr[0] = pack_h2(ia0.x * ja0, ia0.y * ja0);
            afr[1] = pack_h2(ia1.x * ja1, ia1.y * ja1);
            afr[2] = pack_h2(ib0.x * jb0, ib0.y * jb0);
            afr[3] = pack_h2(ib1.x * jb1, ib1.y * jb1);
            int o0 = ob[ks][0], o1 = ob[ks][1];
#pragma unroll
            for (int t = 0; t < 13; ++t) {
                uint32_t bb0 = spu[o0 + t * 128];
                uint32_t bb1 = spu[o1 + t * 128];
                mma_f16(acc[t], afr, bb0, bb1);
            }
        }
    }

    // ---- reduce the two k-halves through smem (reuse B buffer) ----
    __syncthreads();                       // all warps done reading B
    float* red = (float*)(smem + SP_OFF);  // 64 rows x 104 cols fp32 = 26624 B
    int cb = 2 * tc;
    int rloc = R0 + gid;
    if (wh == 1) {
#pragma unroll
        for (int t = 0; t < 13; ++t) {
            int n0 = cb + t * 8;
            *(float2*)&red[rloc * 104 + n0] = make_float2(acc[t][0], acc[t][1]);
            *(float2*)&red[(rloc + 8) * 104 + n0] = make_float2(acc[t][2], acc[t][3]);
        }
    }
    __syncthreads();
    if (wh == 0) {
        int r = b0 + rloc;
#pragma unroll
        for (int t = 0; t < 13; ++t) {
            int n0 = cb + t * 8;
            if (n0 < NK) {
                float2 p0 = *(float2*)&red[rloc * 104 + n0];
                float2 p1 = *(float2*)&red[(rloc + 8) * 104 + n0];
                *(float2*)&g_term1[(size_t)r * NK + n0] =
                    make_float2(acc[t][0] + p0.x, acc[t][1] + p0.y);
                *(float2*)&g_term1[(size_t)(r + 8) * NK + n0] =
                    make_float2(acc[t][2] + p1.x, acc[t][3] + p1.y);
            }
        }
    }
}

// ---------------- hidden: h = lrelu(lrelu(term1) @ l1W^T + b), tf32 mma ----------------
#define HA_STR 108
#define HB_STR 136
#define HB_OFF 55296
#define SMEM_HID (HB_OFF + 104 * HB_STR * 4)

__global__ void __launch_bounds__(256) k_hid(const float* __restrict__ l1_b) {
    extern __shared__ char sm2[];
    float*    As = (float*)sm2;
    uint32_t* Bs = (uint32_t*)(sm2 + HB_OFF);
    int tid = threadIdx.x, lane = tid & 31, wid = tid >> 5;
    int b0 = blockIdx.x * 128, m0 = blockIdx.y * 128;

    for (int i = tid; i < 3328; i += 256) {
        int r = i >> 5, q = i & 31;
        CP_ASYNC16(smem_u32(&Bs[r * HB_STR + q * 4]),
                   (const char*)(g_l1WT + r * H1 + m0 + q * 4));
    }
    CP_COMMIT();

    {
        int r = tid >> 1, hf = tid & 1;
        const float* src = g_term1 + (size_t)(b0 + r) * NK;
        float* dst = As + r * HA_STR;
#pragma unroll 4
        for (int q = 0; q < 52; ++q) {
            int cc = hf * 52 + q;
            float v = (cc < NK) ? lrelu(src[cc]) : 0.f;
            dst[cc] = __uint_as_float(f2tf32(v));
        }
    }
    asm volatile("cp.async.wait_group 0;" ::: "memory");
    __syncthreads();

    int rw = wid & 3, cw = wid >> 2;
    int R0 = rw * 32;
    int ic = lane & 3;

    float acc[2][8][4];
#pragma unroll
    for (int f = 0; f < 2; ++f)
#pragma unroll
        for (int t = 0; t < 8; ++t)
#pragma unroll
            for (int q = 0; q < 4; ++q) acc[f][t][q] = 0.f;

#pragma unroll
    for (int kk = 0; kk < 13; ++kk) {
        uint32_t af[2][4];
#pragma unroll
        for (int f = 0; f < 2; ++f) {
            const uint32_t* hp = (const uint32_t*)As +
                (R0 + f * 16 + (lane >> 2)) * HA_STR + kk * 8 + ic;
            af[f][0] = hp[0];
            af[f][1] = hp[8 * HA_STR];
            af[f][2] = hp[4];
            af[f][3] = hp[8 * HA_STR + 4];
        }
        const uint32_t* wp = &Bs[(kk * 8 + ic) * HB_STR + cw * 64 + (lane >> 2)];
#pragma unroll
        for (int t = 0; t < 8; ++t) {
            uint32_t bb0 = wp[t * 8];
            uint32_t bb1 = wp[4 * HB_STR + t * 8];
            mma_tf32(acc[0][t], af[0], bb0, bb1);
            mma_tf32(acc[1][t], af[1], bb0, bb1);
        }
    }

#pragma unroll
    for (int t = 0; t < 8; ++t) {
        int m = m0 + cw * 64 + t * 8 + 2 * ic;
        float bm0 = l1_b[m], bm1 = l1_b[m + 1];
#pragma unroll
        for (int f = 0; f < 2; ++f) {
            int r = b0 + R0 + f * 16 + (lane >> 2);
            g_hu[(size_t)r * 256 + (m >> 1)] =
                pack_h2(lrelu(acc[f][t][0] + bm0), lrelu(acc[f][t][1] + bm1));
            g_hu[(size_t)(r + 8) * 256 + (m >> 1)] =
                pack_h2(lrelu(acc[f][t][2] + bm0), lrelu(acc[f][t][3] + bm1));
        }
    }
}

// ---------------- l2 GEMM via mma.sync fp16 ----------------
#define L2_STR 12   // words per row (8 used + 4 pad)
__global__ void __launch_bounds__(256) k_l2_mma(const float* __restrict__ l2_b,
                                                float* __restrict__ out) {
    __shared__ uint32_t hs[2][128 * L2_STR];
    __shared__ uint32_t ws[2][128 * L2_STR];
    int tid = threadIdx.x, lane = tid & 31, wid = tid >> 5;
    int b0 = blockIdx.x * 128, e0 = blockIdx.y * 128;
    int rw = wid & 3, cw = wid >> 2;
    int R0 = rw * 32;
    int gid = lane >> 2, tc = lane & 3;

    float acc[2][8][4];
#pragma unroll
    for (int f = 0; f < 2; ++f)
#pragma unroll
        for (int t = 0; t < 8; ++t)
#pragma unroll
            for (int q = 0; q < 4; ++q) acc[f][t][q] = 0.f;

    auto issue = [&](int kt, int s) {
        {
            int r = tid >> 1, q = tid & 1;
            const char* src = (const char*)(g_hu + (size_t)(b0 + r) * 256 + kt * 8) + q * 16;
            CP_ASYNC16(smem_u32(&hs[s][r * L2_STR]) + q * 16, src);
        }
        {
            int r = tid >> 1, q = tid & 1;
            const char* src = (const char*)g_l2Wh + ((size_t)(e0 + r) * 512 + kt * 16) * 2 + q * 16;
            CP_ASYNC16(smem_u32(&ws[s][r * L2_STR]) + q * 16, src);
        }
        CP_COMMIT();
    };
    issue(0, 0);

    for (int kt = 0; kt < 32; ++kt) {
        int s = kt & 1;
        if (kt + 1 < 32) {
            issue(kt + 1, s ^ 1);
            asm volatile("cp.async.wait_group 1;" ::: "memory");
        } else {
            asm volatile("cp.async.wait_group 0;" ::: "memory");
        }
        __syncthreads();

        uint32_t af[2][4];
#pragma unroll
        for (int f = 0; f < 2; ++f) {
            const uint32_t* hp = &hs[s][(R0 + f * 16 + gid) * L2_STR];
            af[f][0] = hp[tc];
            af[f][1] = hp[8 * L2_STR + tc];
            af[f][2] = hp[tc + 4];
            af[f][3] = hp[8 * L2_STR + tc + 4];
        }
        const uint32_t* wp = &ws[s][(cw * 64 + gid) * L2_STR];
#pragma unroll
        for (int t = 0; t < 8; ++t) {
            uint32_t bb0 = wp[t * 8 * L2_STR + tc];
            uint32_t bb1 = wp[t * 8 * L2_STR + tc + 4];
            mma_f16(acc[0][t], af[0], bb0, bb1);
            mma_f16(acc[1][t], af[1], bb0, bb1);
        }
        __syncthreads();
    }

#pragma unroll
    for (int t = 0; t < 8; ++t) {
        int e = e0 + cw * 64 + t * 8 + 2 * tc;
        float be0 = l2_b[e], be1 = l2_b[e + 1];
#pragma unroll
        for (int f = 0; f < 2; ++f) {
            int r = b0 + R0 + f * 16 + gid;
            *(float2*)&out[(size_t)r * EM + e] =
                make_float2(acc[f][t][0] + be0, acc[f][t][1] + be1);
            *(float2*)&out[(size_t)(r + 8) * EM + e] =
                make_float2(acc[f][t][2] + be0, acc[f][t][3] + be1);
        }
    }
}

// ---------------- row-wise L2 normalization ----------------
__global__ void __launch_bounds__(256) k_norm(float* __restrict__ out) {
    __shared__ float wsum[8];
    int b = blockIdx.x;
    int t = threadIdx.x;
    float4* row = (float4*)(out + (size_t)b * EM);
    float4 v = row[t];
    float s = v.x * v.x + v.y * v.y + v.z * v.z + v.w * v.w;
#pragma unroll
    for (int off = 16; off > 0; off >>= 1)
        s += __shfl_xor_sync(0xffffffffu, s, off);
    if ((t & 31) == 0) wsum[t >> 5] = s;
    __syncthreads();
    float tot = wsum[0] + wsum[1] + wsum[2] + wsum[3] +
                wsum[4] + wsum[5] + wsum[6] + wsum[7];
    float inv = rsqrtf(tot);
    row[t] = make_float4(v.x * inv, v.y * inv, v.z * inv, v.w * inv);
}

// ---------------- launch ----------------
extern "C" void kernel_launch(void* const* d_in, const int* in_sizes, int n_in,
                              void* d_out, int out_size) {
    const int*   x       = (const int*)d_in[0];
    const float* embed_W = (const float*)d_in[2];
    const float* pd_W    = (const float*)d_in[3];
    const float* pd_b    = (const float*)d_in[4];
    const float* comp_T  = (const float*)d_in[5];
    const float* cl_W    = (const float*)d_in[6];
    const float* cl_b    = (const float*)d_in[7];
    const float* l1_W    = (const float*)d_in[8];
    const float* l1_b    = (const float*)d_in[9];
    const float* l2_W    = (const float*)d_in[10];
    const float* l2_b    = (const float*)d_in[11];
    float* out = (float*)d_out;

    k_prep_groups<<<1, 256>>>();
    k_prep_small<<<128, 256>>>(pd_W, l1_W);
    k_prep_spb<<<NC32, 256>>>(comp_T, cl_W, cl_b);
    k_prep_l2h<<<(H1 * EM) / 256, 256>>>(l2_W);
    k_cat<<<(2 * BATCH) / 16, 256>>>(x, embed_W, pd_b);

    cudaFuncSetAttribute(k_main_mma, cudaFuncAttributeMaxDynamicSharedMemorySize,
                         SMEM_MAIN);
    k_main_mma<<<BATCH / 64, 256, SMEM_MAIN>>>();

    cudaFuncSetAttribute(k_hid, cudaFuncAttributeMaxDynamicSharedMemorySize,
                         SMEM_HID);
    k_hid<<<dim3(BATCH / 128, 4), 256, SMEM_HID>>>(l1_b);

    k_l2_mma<<<dim3(BATCH / 128, EM / 128), 256>>>(l2_b, out);
    k_norm<<<BATCH, 256>>>(out);
}

// round 12
// speedup vs baseline: 1.0978x; 1.0978x over previous
#include <cuda_runtime.h>
#include <cuda_fp16.h>
#include <cstdint>

#define BATCH 16384
#define NK 100        // TENSOR_DIM
#define D 200         // 2*TENSOR_DIM
#define H1 512        // EMBED_SIZE/2
#define EM 1024       // EMBED_SIZE
#define WD 300        // WORD_DIM

#define PREAL 20400   // real quadratic pair count
#define PLIN  20600   // + 200 linear (term2) pairs
#define PPAD  20608   // padded to 32 (20600 = cl_b pair, rest zero)
#define NGROUP 5152   // PPAD / 4
#define NC32 644      // PPAD / 32
#define NCC  322      // chunk pairs
#define SPB_CHUNK 7680   // 120 n-rows * 32 p * 2B (global layout)
#define SPC 6656         // 104 n-rows * 64B (compact smem chunk)

// ---------------- scratch (device globals; no allocation) ----------------
__device__ float g_catT[D * BATCH];               // cat transposed [i][b]
__device__ unsigned char g_SpB[NC32 * SPB_CHUNK]; // Sp fp16, swizzled [c][n][p]
__device__ int2  g_groups[NGROUP];                // (j, i0) per 4-pair group
__device__ uint16_t g_gpk[NGROUP];                // packed (i0<<8)|j
__device__ float g_pdWT[WD * NK];
__device__ float g_l1WT[104 * H1];                // [k][m], rows 100..103 zero
__device__ unsigned char g_l2Wh[EM * H1 * 2];     // l2_W fp16 [e][k]
__device__ float g_term1[BATCH * NK];             // term1+term2+cl_b (pre-lrelu)
__device__ uint32_t g_hu[BATCH * 256];            // h as packed half2 [b][256]

__device__ __forceinline__ float lrelu(float x) { return x >= 0.f ? x : 0.1f * x; }

__device__ __forceinline__ uint32_t smem_u32(const void* p) {
    return (uint32_t)__cvta_generic_to_shared(p);
}
__device__ __forceinline__ uint32_t f2tf32(float x) {
    uint32_t r; asm("cvt.rna.tf32.f32 %0, %1;" : "=r"(r) : "f"(x)); return r;
}
__device__ __forceinline__ uint32_t pack_h2(float lo, float hi) {
    __half2 h = __floats2half2_rn(lo, hi);
    return *(uint32_t*)&h;
}
#define CP_ASYNC16(dst, src) \
    asm volatile("cp.async.cg.shared.global [%0], [%1], 16;" :: "r"(dst), "l"(src) : "memory")
#define CP_COMMIT() asm volatile("cp.async.commit_group;" ::: "memory")

__device__ __forceinline__ void mma_tf32(float* d, const uint32_t* a,
                                         uint32_t b0, uint32_t b1) {
    asm volatile(
        "mma.sync.aligned.m16n8k8.row.col.f32.tf32.tf32.f32 "
        "{%0,%1,%2,%3}, {%4,%5,%6,%7}, {%8,%9}, {%0,%1,%2,%3};"
        : "+f"(d[0]), "+f"(d[1]), "+f"(d[2]), "+f"(d[3])
        : "r"(a[0]), "r"(a[1]), "r"(a[2]), "r"(a[3]), "r"(b0), "r"(b1));
}
__device__ __forceinline__ void mma_f16(float* d, const uint32_t* a,
                                        uint32_t b0, uint32_t b1) {
    asm volatile(
        "mma.sync.aligned.m16n8k16.row.col.f32.f16.f16.f32 "
        "{%0,%1,%2,%3}, {%4,%5,%6,%7}, {%8,%9}, {%0,%1,%2,%3};"
        : "+f"(d[0]), "+f"(d[1]), "+f"(d[2]), "+f"(d[3])
        : "r"(a[0]), "r"(a[1]), "r"(a[2]), "r"(a[3]), "r"(b0), "r"(b1));
}

// ================= fused prep 1: groups + small transposes + l2 half =======
// bid 0            -> pair-group tables
// bid 1..128       -> pdWT / l1WT transposes
// bid 129..2176    -> l2_W fp16 convert
__global__ void __launch_bounds__(256) k_pre1(const float* __restrict__ pd_W,
                                              const float* __restrict__ l1_W,
                                              const float* __restrict__ l2_W) {
    int bid = blockIdx.x;
    int tid = threadIdx.x;
    if (bid == 0) {
        int j = tid;
        if (j < 200) {
            int q = j >> 2, r = j & 3;
            int S = 2 * q * (q - 1) + r * q;
            int gbase = 50 * j - S;
            int i0 = j & ~3;
            int ng = (200 - i0) >> 2;
            for (int g = 0; g < ng; ++g) {
                int ii = i0 + 4 * g;
                g_groups[gbase + g] = make_int2(j, ii);
                g_gpk[gbase + g] = (uint16_t)((ii << 8) | j);
            }
        }
        int idx = j - 200;
        if (idx >= 0 && idx < 50) {
            g_groups[5100 + idx] = make_int2(200, idx * 4);
            g_gpk[5100 + idx] = (uint16_t)(((idx * 4) << 8) | 200);
        }
        if (idx == 50) { g_groups[5150] = make_int2(200, 200);
                         g_gpk[5150] = (uint16_t)((200 << 8) | 200); }
        if (idx == 51) { g_groups[5151] = make_int2(200, 204);
                         g_gpk[5151] = (uint16_t)((204 << 8) | 200); }
    } else if (bid <= 128) {
        int stride = 128 * 256;
        int t0 = (bid - 1) * 256 + tid;
        for (int l = t0; l < WD * NK; l += stride) {
            int c = l / NK, k = l - c * NK;
            g_pdWT[l] = pd_W[k * WD + c];
        }
        for (int l = t0; l < NK * H1; l += stride) {
            int k = l / H1, m = l - k * H1;
            g_l1WT[l] = l1_W[m * NK + k];
        }
    } else {
        int idx = (bid - 129) * 256 + tid;       // e*512 + k
        ((__half*)g_l2Wh)[idx] = __float2half_rn(l2_W[idx]);
    }
}

// ================= fused prep 2: Sp pack + cat (embedding+projdown) ========
// bid 0..643      -> Sp fp16 pack (needs g_groups from pre1)
// bid 644..2691   -> cat (needs g_pdWT from pre1)
__global__ void __launch_bounds__(256) k_pre2(const float* __restrict__ T,
                                              const float* __restrict__ clW,
                                              const float* __restrict__ clb,
                                              const int* __restrict__ x,
                                              const float* __restrict__ embed_W,
                                              const float* __restrict__ pd_b) {
    __shared__ float e_s[16][WD + 4];
    __shared__ float o_s[NK][17];
    __shared__ int   xs[16];
    int bid = blockIdx.x;
    int t = threadIdx.x;

    if (bid < NC32) {
        // ---- Sp pack ----
        int c = bid;
        unsigned char* base = g_SpB + (size_t)c * SPB_CHUNK;
        for (int e = t; e < 3840; e += 256) {
            int n = e >> 5, pl = e & 31;
            int p = c * 32 + pl;
            float v = 0.f;
            if (n < NK) {
                if (p < PREAL) {
                    int2 gi = g_groups[p >> 2];
                    int i = gi.y + (p & 3), j = gi.x;
                    if (i > j)       v = T[(n * D + i) * D + j] + T[(n * D + j) * D + i];
                    else if (i == j) v = T[(n * D + i) * D + i];
                } else if (p < PLIN) {
                    v = clW[n * D + (p - PREAL)];
                } else if (p == PLIN) {
                    v = clb[n];
                }
            }
            int w = pl >> 1;
            int sg = ((n >> 1) & 3) << 2;
            int off = n * 64 + ((w ^ sg) << 2) + (pl & 1) * 2;
            *(__half*)(base + off) = __float2half_rn(v);
        }
        return;
    }

    // ---- cat ----
    int g = bid - NC32;
    int row0 = g * 16;
    int slot = row0 / BATCH;
    int bbase = row0 - slot * BATCH;
    if (t < 16) xs[t] = x[(bbase + t) * 2 + slot];
    __syncthreads();
    for (int l = t; l < 16 * WD; l += 256) {
        int r = l / WD, c = l - r * WD;
        e_s[r][c] = embed_W[(size_t)xs[r] * WD + c];
    }
    __syncthreads();
    int k  = t & 127;
    int rt = t >> 7;
    if (k < NK) {
        float acc[8];
#pragma unroll
        for (int q = 0; q < 8; ++q) acc[q] = 0.f;
        for (int c4 = 0; c4 < WD; c4 += 4) {
            float w0 = g_pdWT[(c4 + 0) * NK + k];
            float w1 = g_pdWT[(c4 + 1) * NK + k];
            float w2 = g_pdWT[(c4 + 2) * NK + k];
            float w3 = g_pdWT[(c4 + 3) * NK + k];
#pragma unroll
            for (int q = 0; q < 8; ++q) {
                float4 e = *(const float4*)&e_s[rt + 2 * q][c4];
                acc[q] += e.x * w0 + e.y * w1 + e.z * w2 + e.w * w3;
            }
        }
        float bk = pd_b[k];
#pragma unroll
        for (int q = 0; q < 8; ++q)
            o_s[k][rt + 2 * q] = lrelu(acc[q] + bk);
    }
    __syncthreads();
    for (int l = t; l < NK * 16; l += 256) {
        int kk = l >> 4, col = l & 15;
        g_catT[(slot * NK + kk) * BATCH + bbase + col] = o_s[kk][col];
    }
}

// ---------------- main: term1(+term2+bias) via mma.sync fp16 ----------------
// CTA: 64 b x 104 n, 4 warps, 2 CTAs/SM. 64 pairs (2 chunks) per iteration,
// ONE __syncthreads per iteration; 2 mega-buffers (skew<=1 makes it safe).
#define CAT_STRIDE 228                          // words
#define SP_OFF   58368                          // 64 * 228 * 4
#define GRP_OFF  (SP_OFF + 2 * 2 * SPC)         // 58368 + 26624 = 84992
#define SMEM_MAIN (GRP_OFF + NGROUP * 2)        // 95296
#define BLOAD2 832                              // 2 chunks * 416 x 16B

__global__ void __launch_bounds__(128, 2) k_main_mma() {
    extern __shared__ char smem[];
    float* cat = (float*)smem;
    uint16_t* grp = (uint16_t*)(smem + GRP_OFF);
    uint32_t sb = smem_u32(smem);
    int tid = threadIdx.x, lane = tid & 31, wid = tid >> 5;
    int b0 = blockIdx.x * 64;

    // prologue: kick off pair 0 load into slot 0
    {
        const char* src = (const char*)g_SpB;
        for (int i = tid; i < BLOAD2; i += 128) {
            int ch = i / 416, off = i - ch * 416;
            CP_ASYNC16(sb + SP_OFF + ch * SPC + off * 16,
                       src + (size_t)ch * SPB_CHUNK + off * 16);
        }
        CP_COMMIT();
    }
    for (int l = tid; l < NGROUP / 2; l += 128)
        ((uint32_t*)grp)[l] = ((const uint32_t*)g_gpk)[l];
    for (int l = tid; l < D * 64; l += 128) {
        int i = l >> 6, b = l & 63;
        cat[b * CAT_STRIDE + i] = g_catT[i * BATCH + b0 + b];
    }
    if (tid < 64) {   // ones column + zero pad (slots 200..207)
        float* r = cat + tid * CAT_STRIDE;
        r[200] = 1.f;
#pragma unroll
        for (int s = 201; s < 208; ++s) r[s] = 0.f;
    }

    int gid = lane >> 2;      // 0..7
    int tc  = lane & 3;       // 0..3
    int R0 = wid * 16;
    int rA = R0 + gid;
    int oa = (tc & 1) * 2;    // i offset within group
    int gsel = tc >> 1;       // which of 2 sub-groups
    // B word offsets (conflict-free via block swizzle)
    int sgB = ((gid >> 1) & 3) << 2;
    int ob[2][2];
#pragma unroll
    for (int s = 0; s < 2; ++s) {
        ob[s][0] = gid * 16 + ((s * 8 + tc) ^ sgB);
        ob[s][1] = gid * 16 + ((s * 8 + tc + 4) ^ sgB);
    }

    float acc[13][4];
#pragma unroll
    for (int t = 0; t < 13; ++t)
#pragma unroll
        for (int q = 0; q < 4; ++q) acc[t][q] = 0.f;

    const float* r0 = cat + rA * CAT_STRIDE;
    const float* r1 = r0 + 8 * CAT_STRIDE;

    for (int cc = 0; cc < NCC; ++cc) {
        int slot = cc & 1;
        asm volatile("cp.async.wait_group 0;" ::: "memory");
        __syncthreads();   // pair cc visible; everyone done with other slot
        if (cc + 1 < NCC) {
            const char* src = (const char*)g_SpB + (size_t)(cc + 1) * 2 * SPB_CHUNK;
            uint32_t dst = sb + SP_OFF + (slot ^ 1) * 2 * SPC;
            for (int i = tid; i < BLOAD2; i += 128) {
                int ch = i / 416, off = i - ch * 416;
                CP_ASYNC16(dst + ch * SPC + off * 16,
                           src + (size_t)ch * SPB_CHUNK + off * 16);
            }
            CP_COMMIT();
        }

#pragma unroll
        for (int k = 0; k < 2; ++k) {     // 2 chunks in this pair
            int c = cc * 2 + k;
            const uint32_t* spu =
                (const uint32_t*)(smem + SP_OFF + slot * 2 * SPC + k * SPC);
            int gb = c * 8;
#pragma unroll
            for (int ks = 0; ks < 2; ++ks) {   // two k16 steps per chunk
                int ga  = grp[gb + ks * 4 + gsel];
                int gb_ = grp[gb + ks * 4 + 2 + gsel];
                int ja = ga & 255,  ia = ga >> 8;
                int jb = gb_ & 255, ib = gb_ >> 8;
                float  ja0 = r0[ja], ja1 = r1[ja];
                float  jb0 = r0[jb], jb1 = r1[jb];
                float2 ia0 = *(const float2*)&r0[ia + oa];
                float2 ia1 = *(const float2*)&r1[ia + oa];
                float2 ib0 = *(const float2*)&r0[ib + oa];
                float2 ib1 = *(const float2*)&r1[ib + oa];
                uint32_t afr[4];
                afr[0] = pack_h2(ia0.x * ja0, ia0.y * ja0);
                afr[1] = pack_h2(ia1.x * ja1, ia1.y * ja1);
                afr[2] = pack_h2(ib0.x * jb0, ib0.y * jb0);
                afr[3] = pack_h2(ib1.x * jb1, ib1.y * jb1);
                int o0 = ob[ks][0], o1 = ob[ks][1];
#pragma unroll
                for (int t = 0; t < 13; ++t) {
                    uint32_t bb0 = spu[o0 + t * 128];
                    uint32_t bb1 = spu[o1 + t * 128];
                    mma_f16(acc[t], afr, bb0, bb1);
                }
            }
        }
    }

    // epilogue: write term1 (cols < 100)
    int cb = 2 * tc;
    int r = b0 + R0 + gid;
#pragma unroll
    for (int t = 0; t < 13; ++t) {
        int n0 = cb + t * 8;
        if (n0 < NK) {
            *(float2*)&g_term1[(size_t)r * NK + n0] =
                make_float2(acc[t][0], acc[t][1]);
            *(float2*)&g_term1[(size_t)(r + 8) * NK + n0] =
                make_float2(acc[t][2], acc[t][3]);
        }
    }
}

// ---------------- hidden: h = lrelu(lrelu(term1) @ l1W^T + b), tf32 mma ----------------
#define HA_STR 108
#define HB_STR 136
#define HB_OFF 55296
#define SMEM_HID (HB_OFF + 104 * HB_STR * 4)

__global__ void __launch_bounds__(256) k_hid(const float* __restrict__ l1_b) {
    extern __shared__ char sm2[];
    float*    As = (float*)sm2;
    uint32_t* Bs = (uint32_t*)(sm2 + HB_OFF);
    int tid = threadIdx.x, lane = tid & 31, wid = tid >> 5;
    int b0 = blockIdx.x * 128, m0 = blockIdx.y * 128;

    for (int i = tid; i < 3328; i += 256) {
        int r = i >> 5, q = i & 31;
        CP_ASYNC16(smem_u32(&Bs[r * HB_STR + q * 4]),
                   (const char*)(g_l1WT + r * H1 + m0 + q * 4));
    }
    CP_COMMIT();

    {
        int r = tid >> 1, hf = tid & 1;
        const float* src = g_term1 + (size_t)(b0 + r) * NK;
        float* dst = As + r * HA_STR;
#pragma unroll 4
        for (int q = 0; q < 52; ++q) {
            int cc = hf * 52 + q;
            float v = (cc < NK) ? lrelu(src[cc]) : 0.f;
            dst[cc] = __uint_as_float(f2tf32(v));
        }
    }
    asm volatile("cp.async.wait_group 0;" ::: "memory");
    __syncthreads();

    int rw = wid & 3, cw = wid >> 2;
    int R0 = rw * 32;
    int ic = lane & 3;

    float acc[2][8][4];
#pragma unroll
    for (int f = 0; f < 2; ++f)
#pragma unroll
        for (int t = 0; t < 8; ++t)
#pragma unroll
            for (int q = 0; q < 4; ++q) acc[f][t][q] = 0.f;

#pragma unroll
    for (int kk = 0; kk < 13; ++kk) {
        uint32_t af[2][4];
#pragma unroll
        for (int f = 0; f < 2; ++f) {
            const uint32_t* hp = (const uint32_t*)As +
                (R0 + f * 16 + (lane >> 2)) * HA_STR + kk * 8 + ic;
            af[f][0] = hp[0];
            af[f][1] = hp[8 * HA_STR];
            af[f][2] = hp[4];
            af[f][3] = hp[8 * HA_STR + 4];
        }
        const uint32_t* wp = &Bs[(kk * 8 + ic) * HB_STR + cw * 64 + (lane >> 2)];
#pragma unroll
        for (int t = 0; t < 8; ++t) {
            uint32_t bb0 = wp[t * 8];
            uint32_t bb1 = wp[4 * HB_STR + t * 8];
            mma_tf32(acc[0][t], af[0], bb0, bb1);
            mma_tf32(acc[1][t], af[1], bb0, bb1);
        }
    }

#pragma unroll
    for (int t = 0; t < 8; ++t) {
        int m = m0 + cw * 64 + t * 8 + 2 * ic;
        float bm0 = l1_b[m], bm1 = l1_b[m + 1];
#pragma unroll
        for (int f = 0; f < 2; ++f) {
            int r = b0 + R0 + f * 16 + (lane >> 2);
            g_hu[(size_t)r * 256 + (m >> 1)] =
                pack_h2(lrelu(acc[f][t][0] + bm0), lrelu(acc[f][t][1] + bm1));
            g_hu[(size_t)(r + 8) * 256 + (m >> 1)] =
                pack_h2(lrelu(acc[f][t][2] + bm0), lrelu(acc[f][t][3] + bm1));
        }
    }
}

// ---------------- l2 GEMM via mma.sync fp16 ----------------
#define L2_STR 12   // words per row (8 used + 4 pad)
__global__ void __launch_bounds__(256) k_l2_mma(const float* __restrict__ l2_b,
                                                float* __restrict__ out) {
    __shared__ uint32_t hs[2][128 * L2_STR];
    __shared__ uint32_t ws[2][128 * L2_STR];
    int tid = threadIdx.x, lane = tid & 31, wid = tid >> 5;
    int b0 = blockIdx.x * 128, e0 = blockIdx.y * 128;
    int rw = wid & 3, cw = wid >> 2;
    int R0 = rw * 32;
    int gid = lane >> 2, tc = lane & 3;

    float acc[2][8][4];
#pragma unroll
    for (int f = 0; f < 2; ++f)
#pragma unroll
        for (int t = 0; t < 8; ++t)
#pragma unroll
            for (int q = 0; q < 4; ++q) acc[f][t][q] = 0.f;

    auto issue = [&](int kt, int s) {
        {
            int r = tid >> 1, q = tid & 1;
            const char* src = (const char*)(g_hu + (size_t)(b0 + r) * 256 + kt * 8) + q * 16;
            CP_ASYNC16(smem_u32(&hs[s][r * L2_STR]) + q * 16, src);
        }
        {
            int r = tid >> 1, q = tid & 1;
            const char* src = (const char*)g_l2Wh + ((size_t)(e0 + r) * 512 + kt * 16) * 2 + q * 16;
            CP_ASYNC16(smem_u32(&ws[s][r * L2_STR]) + q * 16, src);
        }
        CP_COMMIT();
    };
    issue(0, 0);

    for (int kt = 0; kt < 32; ++kt) {
        int s = kt & 1;
        if (kt + 1 < 32) {
            issue(kt + 1, s ^ 1);
            asm volatile("cp.async.wait_group 1;" ::: "memory");
        } else {
            asm volatile("cp.async.wait_group 0;" ::: "memory");
        }
        __syncthreads();

        uint32_t af[2][4];
#pragma unroll
        for (int f = 0; f < 2; ++f) {
            const uint32_t* hp = &hs[s][(R0 + f * 16 + gid) * L2_STR];
            af[f][0] = hp[tc];
            af[f][1] = hp[8 * L2_STR + tc];
            af[f][2] = hp[tc + 4];
            af[f][3] = hp[8 * L2_STR + tc + 4];
        }
        const uint32_t* wp = &ws[s][(cw * 64 + gid) * L2_STR];
#pragma unroll
        for (int t = 0; t < 8; ++t) {
            uint32_t bb0 = wp[t * 8 * L2_STR + tc];
            uint32_t bb1 = wp[t * 8 * L2_STR + tc + 4];
            mma_f16(acc[0][t], af[0], bb0, bb1);
            mma_f16(acc[1][t], af[1], bb0, bb1);
        }
        __syncthreads();
    }

#pragma unroll
    for (int t = 0; t < 8; ++t) {
        int e = e0 + cw * 64 + t * 8 + 2 * tc;
        float be0 = l2_b[e], be1 = l2_b[e + 1];
#pragma unroll
        for (int f = 0; f < 2; ++f) {
            int r = b0 + R0 + f * 16 + gid;
            *(float2*)&out[(size_t)r * EM + e] =
                make_float2(acc[f][t][0] + be0, acc[f][t][1] + be1);
            *(float2*)&out[(size_t)(r + 8) * EM + e] =
                make_float2(acc[f][t][2] + be0, acc[f][t][3] + be1);
        }
    }
}

// ---------------- row-wise L2 normalization ----------------
__global__ void __launch_bounds__(256) k_norm(float* __restrict__ out) {
    __shared__ float wsum[8];
    int b = blockIdx.x;
    int t = threadIdx.x;
    float4* row = (float4*)(out + (size_t)b * EM);
    float4 v = row[t];
    float s = v.x * v.x + v.y * v.y + v.z * v.z + v.w * v.w;
#pragma unroll
    for (int off = 16; off > 0; off >>= 1)
        s += __shfl_xor_sync(0xffffffffu, s, off);
    if ((t & 31) == 0) wsum[t >> 5] = s;
    __syncthreads();
    float tot = wsum[0] + wsum[1] + wsum[2] + wsum[3] +
                wsum[4] + wsum[5] + wsum[6] + wsum[7];
    float inv = rsqrtf(tot);
    row[t] = make_float4(v.x * inv, v.y * inv, v.z * inv, v.w * inv);
}

// ---------------- launch ----------------
extern "C" void kernel_launch(void* const* d_in, const int* in_sizes, int n_in,
                              void* d_out, int out_size) {
    const int*   x       = (const int*)d_in[0];
    const float* embed_W = (const float*)d_in[2];
    const float* pd_W    = (const float*)d_in[3];
    const float* pd_b    = (const float*)d_in[4];
    const float* comp_T  = (const float*)d_in[5];
    const float* cl_W    = (const float*)d_in[6];
    const float* cl_b    = (const float*)d_in[7];
    const float* l1_W    = (const float*)d_in[8];
    const float* l1_b    = (const float*)d_in[9];
    const float* l2_W    = (const float*)d_in[10];
    const float* l2_b    = (const float*)d_in[11];
    float* out = (float*)d_out;

    // fused preps: pre1 (groups+transposes+l2h), then pre2 (Sp pack ∪ cat)
    k_pre1<<<1 + 128 + (H1 * EM) / 256, 256>>>(pd_W, l1_W, l2_W);
    k_pre2<<<NC32 + (2 * BATCH) / 16, 256>>>(comp_T, cl_W, cl_b,
                                             x, embed_W, pd_b);

    cudaFuncSetAttribute(k_main_mma, cudaFuncAttributeMaxDynamicSharedMemorySize,
                         SMEM_MAIN);
    k_main_mma<<<BATCH / 64, 128, SMEM_MAIN>>>();

    cudaFuncSetAttribute(k_hid, cudaFuncAttributeMaxDynamicSharedMemorySize,
                         SMEM_HID);
    k_hid<<<dim3(BATCH / 128, 4), 256, SMEM_HID>>>(l1_b);

    k_l2_mma<<<dim3(BATCH / 128, EM / 128), 256>>>(l2_b, out);
    k_norm<<<BATCH, 256>>>(out);
}

// round 13
// speedup vs baseline: 1.1312x; 1.0304x over previous
#include <cuda_runtime.h>
#include <cuda_fp16.h>
#include <cstdint>

#define BATCH 16384
#define NK 100        // TENSOR_DIM
#define D 200         // 2*TENSOR_DIM
#define H1 512        // EMBED_SIZE/2
#define EM 1024       // EMBED_SIZE
#define WD 300        // WORD_DIM

#define PREAL 20400   // real quadratic pair count
#define PLIN  20600   // + 200 linear (term2) pairs
#define PPAD  20608   // padded to 32 (20600 = cl_b pair, rest zero)
#define NGROUP 5152   // PPAD / 4
#define NC32 644      // PPAD / 32
#define NCC  322      // chunk pairs
#define SPB_CHUNK 7680   // 120 n-rows * 32 p * 2B (global layout)
#define SPC 6656         // 104 n-rows * 64B (compact smem chunk)
#define T1_STR 104       // term1 row stride (tf32 bits, lrelu pre-applied)

// ---------------- scratch (device globals; no allocation) ----------------
__device__ float g_catT[D * BATCH];               // cat transposed [i][b]
__device__ unsigned char g_SpB[NC32 * SPB_CHUNK]; // Sp fp16, swizzled [c][n][p]
__device__ int2  g_groups[NGROUP];                // (j, i0) per 4-pair group
__device__ uint16_t g_gpk[NGROUP];                // packed (i0<<8)|j
__device__ float g_pdWT[WD * NK];
__device__ float g_l1WT[104 * H1];                // [k][m], rows 100..103 zero
__device__ unsigned char g_l2Wh[EM * H1 * 2];     // l2_W fp16 [e][k]
__device__ float g_term1[BATCH * T1_STR];         // lrelu(term1+term2+b), tf32 bits
__device__ uint32_t g_hu[BATCH * 256];            // h as packed half2 [b][256]

__device__ __forceinline__ float lrelu(float x) { return x >= 0.f ? x : 0.1f * x; }

__device__ __forceinline__ uint32_t smem_u32(const void* p) {
    return (uint32_t)__cvta_generic_to_shared(p);
}
__device__ __forceinline__ uint32_t f2tf32(float x) {
    uint32_t r; asm("cvt.rna.tf32.f32 %0, %1;" : "=r"(r) : "f"(x)); return r;
}
__device__ __forceinline__ uint32_t pack_h2(float lo, float hi) {
    __half2 h = __floats2half2_rn(lo, hi);
    return *(uint32_t*)&h;
}
#define CP_ASYNC16(dst, src) \
    asm volatile("cp.async.cg.shared.global [%0], [%1], 16;" :: "r"(dst), "l"(src) : "memory")
#define CP_COMMIT() asm volatile("cp.async.commit_group;" ::: "memory")

__device__ __forceinline__ void mma_tf32(float* d, const uint32_t* a,
                                         uint32_t b0, uint32_t b1) {
    asm volatile(
        "mma.sync.aligned.m16n8k8.row.col.f32.tf32.tf32.f32 "
        "{%0,%1,%2,%3}, {%4,%5,%6,%7}, {%8,%9}, {%0,%1,%2,%3};"
        : "+f"(d[0]), "+f"(d[1]), "+f"(d[2]), "+f"(d[3])
        : "r"(a[0]), "r"(a[1]), "r"(a[2]), "r"(a[3]), "r"(b0), "r"(b1));
}
__device__ __forceinline__ void mma_f16(float* d, const uint32_t* a,
                                        uint32_t b0, uint32_t b1) {
    asm volatile(
        "mma.sync.aligned.m16n8k16.row.col.f32.f16.f16.f32 "
        "{%0,%1,%2,%3}, {%4,%5,%6,%7}, {%8,%9}, {%0,%1,%2,%3};"
        : "+f"(d[0]), "+f"(d[1]), "+f"(d[2]), "+f"(d[3])
        : "r"(a[0]), "r"(a[1]), "r"(a[2]), "r"(a[3]), "r"(b0), "r"(b1));
}

// ================= fused prep 1: groups + small transposes + l2 half =======
__global__ void __launch_bounds__(256) k_pre1(const float* __restrict__ pd_W,
                                              const float* __restrict__ l1_W,
                                              const float* __restrict__ l2_W) {
    int bid = blockIdx.x;
    int tid = threadIdx.x;
    if (bid == 0) {
        int j = tid;
        if (j < 200) {
            int q = j >> 2, r = j & 3;
            int S = 2 * q * (q - 1) + r * q;
            int gbase = 50 * j - S;
            int i0 = j & ~3;
            int ng = (200 - i0) >> 2;
            for (int g = 0; g < ng; ++g) {
                int ii = i0 + 4 * g;
                g_groups[gbase + g] = make_int2(j, ii);
                g_gpk[gbase + g] = (uint16_t)((ii << 8) | j);
            }
        }
        int idx = j - 200;
        if (idx >= 0 && idx < 50) {
            g_groups[5100 + idx] = make_int2(200, idx * 4);
            g_gpk[5100 + idx] = (uint16_t)(((idx * 4) << 8) | 200);
        }
        if (idx == 50) { g_groups[5150] = make_int2(200, 200);
                         g_gpk[5150] = (uint16_t)((200 << 8) | 200); }
        if (idx == 51) { g_groups[5151] = make_int2(200, 204);
                         g_gpk[5151] = (uint16_t)((204 << 8) | 200); }
    } else if (bid <= 128) {
        int stride = 128 * 256;
        int t0 = (bid - 1) * 256 + tid;
        for (int l = t0; l < WD * NK; l += stride) {
            int c = l / NK, k = l - c * NK;
            g_pdWT[l] = pd_W[k * WD + c];
        }
        for (int l = t0; l < NK * H1; l += stride) {
            int k = l / H1, m = l - k * H1;
            g_l1WT[l] = l1_W[m * NK + k];
        }
    } else {
        int idx = (bid - 129) * 256 + tid;       // e*512 + k
        ((__half*)g_l2Wh)[idx] = __float2half_rn(l2_W[idx]);
    }
}

// ================= fused prep 2: Sp pack + cat (embedding+projdown) ========
__global__ void __launch_bounds__(256) k_pre2(const float* __restrict__ T,
                                              const float* __restrict__ clW,
                                              const float* __restrict__ clb,
                                              const int* __restrict__ x,
                                              const float* __restrict__ embed_W,
                                              const float* __restrict__ pd_b) {
    __shared__ float e_s[16][WD + 4];
    __shared__ float o_s[NK][17];
    __shared__ int   xs[16];
    int bid = blockIdx.x;
    int t = threadIdx.x;

    if (bid < NC32) {
        // ---- Sp pack ----
        int c = bid;
        unsigned char* base = g_SpB + (size_t)c * SPB_CHUNK;
        for (int e = t; e < 3840; e += 256) {
            int n = e >> 5, pl = e & 31;
            int p = c * 32 + pl;
            float v = 0.f;
            if (n < NK) {
                if (p < PREAL) {
                    int2 gi = g_groups[p >> 2];
                    int i = gi.y + (p & 3), j = gi.x;
                    if (i > j)       v = T[(n * D + i) * D + j] + T[(n * D + j) * D + i];
                    else if (i == j) v = T[(n * D + i) * D + i];
                } else if (p < PLIN) {
                    v = clW[n * D + (p - PREAL)];
                } else if (p == PLIN) {
                    v = clb[n];
                }
            }
            int w = pl >> 1;
            int sg = ((n >> 1) & 3) << 2;
            int off = n * 64 + ((w ^ sg) << 2) + (pl & 1) * 2;
            *(__half*)(base + off) = __float2half_rn(v);
        }
        return;
    }

    // ---- cat ----
    int g = bid - NC32;
    int row0 = g * 16;
    int slot = row0 / BATCH;
    int bbase = row0 - slot * BATCH;
    if (t < 16) xs[t] = x[(bbase + t) * 2 + slot];
    __syncthreads();
    for (int l = t; l < 16 * WD; l += 256) {
        int r = l / WD, c = l - r * WD;
        e_s[r][c] = embed_W[(size_t)xs[r] * WD + c];
    }
    __syncthreads();
    int k  = t & 127;
    int rt = t >> 7;
    if (k < NK) {
        float acc[8];
#pragma unroll
        for (int q = 0; q < 8; ++q) acc[q] = 0.f;
        for (int c4 = 0; c4 < WD; c4 += 4) {
            float w0 = g_pdWT[(c4 + 0) * NK + k];
            float w1 = g_pdWT[(c4 + 1) * NK + k];
            float w2 = g_pdWT[(c4 + 2) * NK + k];
            float w3 = g_pdWT[(c4 + 3) * NK + k];
#pragma unroll
            for (int q = 0; q < 8; ++q) {
                float4 e = *(const float4*)&e_s[rt + 2 * q][c4];
                acc[q] += e.x * w0 + e.y * w1 + e.z * w2 + e.w * w3;
            }
        }
        float bk = pd_b[k];
#pragma unroll
        for (int q = 0; q < 8; ++q)
            o_s[k][rt + 2 * q] = lrelu(acc[q] + bk);
    }
    __syncthreads();
    for (int l = t; l < NK * 16; l += 256) {
        int kk = l >> 4, col = l & 15;
        g_catT[(slot * NK + kk) * BATCH + bbase + col] = o_s[kk][col];
    }
}

// ---------------- main: term1(+term2+bias) via mma.sync fp16 ----------------
// CTA: 64 b x 104 n, 4 warps, 2 CTAs/SM. 64 pairs (2 chunks) per iteration.
// Epilogue stores lrelu(term1) as tf32 bits (k_hid consumes via cp.async).
#define CAT_STRIDE 228                          // words
#define SP_OFF   58368                          // 64 * 228 * 4
#define GRP_OFF  (SP_OFF + 2 * 2 * SPC)         // 84992
#define SMEM_MAIN (GRP_OFF + NGROUP * 2)        // 95296
#define BLOAD2 832                              // 2 chunks * 416 x 16B

__global__ void __launch_bounds__(128, 2) k_main_mma() {
    extern __shared__ char smem[];
    float* cat = (float*)smem;
    uint16_t* grp = (uint16_t*)(smem + GRP_OFF);
    uint32_t sb = smem_u32(smem);
    int tid = threadIdx.x, lane = tid & 31, wid = tid >> 5;
    int b0 = blockIdx.x * 64;

    // prologue: kick off pair 0 load into slot 0
    {
        const char* src = (const char*)g_SpB;
        for (int i = tid; i < BLOAD2; i += 128) {
            int ch = i / 416, off = i - ch * 416;
            CP_ASYNC16(sb + SP_OFF + ch * SPC + off * 16,
                       src + (size_t)ch * SPB_CHUNK + off * 16);
        }
        CP_COMMIT();
    }
    for (int l = tid; l < NGROUP / 2; l += 128)
        ((uint32_t*)grp)[l] = ((const uint32_t*)g_gpk)[l];
    for (int l = tid; l < D * 64; l += 128) {
        int i = l >> 6, b = l & 63;
        cat[b * CAT_STRIDE + i] = g_catT[i * BATCH + b0 + b];
    }
    if (tid < 64) {   // ones column + zero pad (slots 200..207)
        float* r = cat + tid * CAT_STRIDE;
        r[200] = 1.f;
#pragma unroll
        for (int s = 201; s < 208; ++s) r[s] = 0.f;
    }

    int gid = lane >> 2;      // 0..7
    int tc  = lane & 3;       // 0..3
    int R0 = wid * 16;
    int rA = R0 + gid;
    int oa = (tc & 1) * 2;    // i offset within group
    int gsel = tc >> 1;       // which of 2 sub-groups
    // B word offsets (conflict-free via block swizzle)
    int sgB = ((gid >> 1) & 3) << 2;
    int ob[2][2];
#pragma unroll
    for (int s = 0; s < 2; ++s) {
        ob[s][0] = gid * 16 + ((s * 8 + tc) ^ sgB);
        ob[s][1] = gid * 16 + ((s * 8 + tc + 4) ^ sgB);
    }

    float acc[13][4];
#pragma unroll
    for (int t = 0; t < 13; ++t)
#pragma unroll
        for (int q = 0; q < 4; ++q) acc[t][q] = 0.f;

    const float* r0 = cat + rA * CAT_STRIDE;
    const float* r1 = r0 + 8 * CAT_STRIDE;

    for (int cc = 0; cc < NCC; ++cc) {
        int slot = cc & 1;
        asm volatile("cp.async.wait_group 0;" ::: "memory");
        __syncthreads();   // pair cc visible; everyone done with other slot
        if (cc + 1 < NCC) {
            const char* src = (const char*)g_SpB + (size_t)(cc + 1) * 2 * SPB_CHUNK;
            uint32_t dst = sb + SP_OFF + (slot ^ 1) * 2 * SPC;
            for (int i = tid; i < BLOAD2; i += 128) {
                int ch = i / 416, off = i - ch * 416;
                CP_ASYNC16(dst + ch * SPC + off * 16,
                           src + (size_t)ch * SPB_CHUNK + off * 16);
            }
            CP_COMMIT();
        }

#pragma unroll
        for (int k = 0; k < 2; ++k) {     // 2 chunks in this pair
            int c = cc * 2 + k;
            const uint32_t* spu =
                (const uint32_t*)(smem + SP_OFF + slot * 2 * SPC + k * SPC);
            int gb = c * 8;
#pragma unroll
            for (int ks = 0; ks < 2; ++ks) {   // two k16 steps per chunk
                int ga  = grp[gb + ks * 4 + gsel];
                int gb_ = grp[gb + ks * 4 + 2 + gsel];
                int ja = ga & 255,  ia = ga >> 8;
                int jb = gb_ & 255, ib = gb_ >> 8;
                float  ja0 = r0[ja], ja1 = r1[ja];
                float  jb0 = r0[jb], jb1 = r1[jb];
                float2 ia0 = *(const float2*)&r0[ia + oa];
                float2 ia1 = *(const float2*)&r1[ia + oa];
                float2 ib0 = *(const float2*)&r0[ib + oa];
                float2 ib1 = *(const float2*)&r1[ib + oa];
                uint32_t afr[4];
                afr[0] = pack_h2(ia0.x * ja0, ia0.y * ja0);
                afr[1] = pack_h2(ia1.x * ja1, ia1.y * ja1);
                afr[2] = pack_h2(ib0.x * jb0, ib0.y * jb0);
                afr[3] = pack_h2(ib1.x * jb1, ib1.y * jb1);
                int o0 = ob[ks][0], o1 = ob[ks][1];
#pragma unroll
                for (int t = 0; t < 13; ++t) {
                    uint32_t bb0 = spu[o0 + t * 128];
                    uint32_t bb1 = spu[o1 + t * 128];
                    mma_f16(acc[t], afr, bb0, bb1);
                }
            }
        }
    }

    // epilogue: write lrelu(term1) as tf32 bits (cols < 100; 100..103 stay 0)
    int cb = 2 * tc;
    int r = b0 + R0 + gid;
#pragma unroll
    for (int t = 0; t < 13; ++t) {
        int n0 = cb + t * 8;
        if (n0 < NK) {
            *(float2*)&g_term1[(size_t)r * T1_STR + n0] = make_float2(
                __uint_as_float(f2tf32(lrelu(acc[t][0]))),
                __uint_as_float(f2tf32(lrelu(acc[t][1]))));
            *(float2*)&g_term1[(size_t)(r + 8) * T1_STR + n0] = make_float2(
                __uint_as_float(f2tf32(lrelu(acc[t][2]))),
                __uint_as_float(f2tf32(lrelu(acc[t][3]))));
        }
    }
}

// ---------------- hidden: h = lrelu(A @ l1W^T + b), tf32 mma ----------------
// A = g_term1 (lrelu+tf32 pre-applied) loaded via cp.async; pure GEMM kernel.
#define HA_STR 108
#define HB_STR 136
#define HB_OFF 55296
#define SMEM_HID (HB_OFF + 104 * HB_STR * 4)

__global__ void __launch_bounds__(256) k_hid(const float* __restrict__ l1_b) {
    extern __shared__ char sm2[];
    float*    As = (float*)sm2;
    uint32_t* Bs = (uint32_t*)(sm2 + HB_OFF);
    int tid = threadIdx.x, lane = tid & 31, wid = tid >> 5;
    int b0 = blockIdx.x * 128, m0 = blockIdx.y * 128;

    // A: 128 rows x 26 float4 chunks (cols 104..107 of HA_STR never read)
    for (int i = tid; i < 3328; i += 256) {
        int r = i / 26, q = i - r * 26;
        CP_ASYNC16(smem_u32(As + r * HA_STR) + q * 16,
                   (const char*)(g_term1 + (size_t)(b0 + r) * T1_STR) + q * 16);
    }
    // B: l1WT rows 0..103, cols m0..m0+127
    for (int i = tid; i < 3328; i += 256) {
        int r = i >> 5, q = i & 31;
        CP_ASYNC16(smem_u32(&Bs[r * HB_STR + q * 4]),
                   (const char*)(g_l1WT + r * H1 + m0 + q * 4));
    }
    CP_COMMIT();
    asm volatile("cp.async.wait_group 0;" ::: "memory");
    __syncthreads();

    int rw = wid & 3, cw = wid >> 2;
    int R0 = rw * 32;
    int ic = lane & 3;

    float acc[2][8][4];
#pragma unroll
    for (int f = 0; f < 2; ++f)
#pragma unroll
        for (int t = 0; t < 8; ++t)
#pragma unroll
            for (int q = 0; q < 4; ++q) acc[f][t][q] = 0.f;

#pragma unroll
    for (int kk = 0; kk < 13; ++kk) {
        uint32_t af[2][4];
#pragma unroll
        for (int f = 0; f < 2; ++f) {
            const uint32_t* hp = (const uint32_t*)As +
                (R0 + f * 16 + (lane >> 2)) * HA_STR + kk * 8 + ic;
            af[f][0] = hp[0];
            af[f][1] = hp[8 * HA_STR];
            af[f][2] = hp[4];
            af[f][3] = hp[8 * HA_STR + 4];
        }
        const uint32_t* wp = &Bs[(kk * 8 + ic) * HB_STR + cw * 64 + (lane >> 2)];
#pragma unroll
        for (int t = 0; t < 8; ++t) {
            uint32_t bb0 = wp[t * 8];
            uint32_t bb1 = wp[4 * HB_STR + t * 8];
            mma_tf32(acc[0][t], af[0], bb0, bb1);
            mma_tf32(acc[1][t], af[1], bb0, bb1);
        }
    }

#pragma unroll
    for (int t = 0; t < 8; ++t) {
        int m = m0 + cw * 64 + t * 8 + 2 * ic;
        float bm0 = l1_b[m], bm1 = l1_b[m + 1];
#pragma unroll
        for (int f = 0; f < 2; ++f) {
            int r = b0 + R0 + f * 16 + (lane >> 2);
            g_hu[(size_t)r * 256 + (m >> 1)] =
                pack_h2(lrelu(acc[f][t][0] + bm0), lrelu(acc[f][t][1] + bm1));
            g_hu[(size_t)(r + 8) * 256 + (m >> 1)] =
                pack_h2(lrelu(acc[f][t][2] + bm0), lrelu(acc[f][t][3] + bm1));
        }
    }
}

// ---------------- l2 GEMM via mma.sync fp16 ----------------
#define L2_STR 12   // words per row (8 used + 4 pad)
__global__ void __launch_bounds__(256) k_l2_mma(const float* __restrict__ l2_b,
                                                float* __restrict__ out) {
    __shared__ uint32_t hs[2][128 * L2_STR];
    __shared__ uint32_t ws[2][128 * L2_STR];
    int tid = threadIdx.x, lane = tid & 31, wid = tid >> 5;
    int b0 = blockIdx.x * 128, e0 = blockIdx.y * 128;
    int rw = wid & 3, cw = wid >> 2;
    int R0 = rw * 32;
    int gid = lane >> 2, tc = lane & 3;

    float acc[2][8][4];
#pragma unroll
    for (int f = 0; f < 2; ++f)
#pragma unroll
        for (int t = 0; t < 8; ++t)
#pragma unroll
            for (int q = 0; q < 4; ++q) acc[f][t][q] = 0.f;

    auto issue = [&](int kt, int s) {
        {
            int r = tid >> 1, q = tid & 1;
            const char* src = (const char*)(g_hu + (size_t)(b0 + r) * 256 + kt * 8) + q * 16;
            CP_ASYNC16(smem_u32(&hs[s][r * L2_STR]) + q * 16, src);
        }
        {
            int r = tid >> 1, q = tid & 1;
            const char* src = (const char*)g_l2Wh + ((size_t)(e0 + r) * 512 + kt * 16) * 2 + q * 16;
            CP_ASYNC16(smem_u32(&ws[s][r * L2_STR]) + q * 16, src);
        }
        CP_COMMIT();
    };
    issue(0, 0);

    for (int kt = 0; kt < 32; ++kt) {
        int s = kt & 1;
        if (kt + 1 < 32) {
            issue(kt + 1, s ^ 1);
            asm volatile("cp.async.wait_group 1;" ::: "memory");
        } else {
            asm volatile("cp.async.wait_group 0;" ::: "memory");
        }
        __syncthreads();

        uint32_t af[2][4];
#pragma unroll
        for (int f = 0; f < 2; ++f) {
            const uint32_t* hp = &hs[s][(R0 + f * 16 + gid) * L2_STR];
            af[f][0] = hp[tc];
            af[f][1] = hp[8 * L2_STR + tc];
            af[f][2] = hp[tc + 4];
            af[f][3] = hp[8 * L2_STR + tc + 4];
        }
        const uint32_t* wp = &ws[s][(cw * 64 + gid) * L2_STR];
#pragma unroll
        for (int t = 0; t < 8; ++t) {
            uint32_t bb0 = wp[t * 8 * L2_STR + tc];
            uint32_t bb1 = wp[t * 8 * L2_STR + tc + 4];
            mma_f16(acc[0][t], af[0], bb0, bb1);
            mma_f16(acc[1][t], af[1], bb0, bb1);
        }
        __syncthreads();
    }

#pragma unroll
    for (int t = 0; t < 8; ++t) {
        int e = e0 + cw * 64 + t * 8 + 2 * tc;
        float be0 = l2_b[e], be1 = l2_b[e + 1];
#pragma unroll
        for (int f = 0; f < 2; ++f) {
            int r = b0 + R0 + f * 16 + gid;
            *(float2*)&out[(size_t)r * EM + e] =
                make_float2(acc[f][t][0] + be0, acc[f][t][1] + be1);
            *(float2*)&out[(size_t)(r + 8) * EM + e] =
                make_float2(acc[f][t][2] + be0, acc[f][t][3] + be1);
        }
    }
}

// ---------------- row-wise L2 normalization ----------------
__global__ void __launch_bounds__(256) k_norm(float* __restrict__ out) {
    __shared__ float wsum[8];
    int b = blockIdx.x;
    int t = threadIdx.x;
    float4* row = (float4*)(out + (size_t)b * EM);
    float4 v = row[t];
    float s = v.x * v.x + v.y * v.y + v.z * v.z + v.w * v.w;
#pragma unroll
    for (int off = 16; off > 0; off >>= 1)
        s += __shfl_xor_sync(0xffffffffu, s, off);
    if ((t & 31) == 0) wsum[t >> 5] = s;
    __syncthreads();
    float tot = wsum[0] + wsum[1] + wsum[2] + wsum[3] +
                wsum[4] + wsum[5] + wsum[6] + wsum[7];
    float inv = rsqrtf(tot);
    row[t] = make_float4(v.x * inv, v.y * inv, v.z * inv, v.w * inv);
}

// ---------------- launch ----------------
extern "C" void kernel_launch(void* const* d_in, const int* in_sizes, int n_in,
                              void* d_out, int out_size) {
    const int*   x       = (const int*)d_in[0];
    const float* embed_W = (const float*)d_in[2];
    const float* pd_W    = (const float*)d_in[3];
    const float* pd_b    = (const float*)d_in[4];
    const float* comp_T  = (const float*)d_in[5];
    const float* cl_W    = (const float*)d_in[6];
    const float* cl_b    = (const float*)d_in[7];
    const float* l1_W    = (const float*)d_in[8];
    const float* l1_b    = (const float*)d_in[9];
    const float* l2_W    = (const float*)d_in[10];
    const float* l2_b    = (const float*)d_in[11];
    float* out = (float*)d_out;

    k_pre1<<<1 + 128 + (H1 * EM) / 256, 256>>>(pd_W, l1_W, l2_W);
    k_pre2<<<NC32 + (2 * BATCH) / 16, 256>>>(comp_T, cl_W, cl_b,
                                             x, embed_W, pd_b);

    cudaFuncSetAttribute(k_main_mma, cudaFuncAttributeMaxDynamicSharedMemorySize,
                         SMEM_MAIN);
    k_main_mma<<<BATCH / 64, 128, SMEM_MAIN>>>();

    cudaFuncSetAttribute(k_hid, cudaFuncAttributeMaxDynamicSharedMemorySize,
                         SMEM_HID);
    k_hid<<<dim3(BATCH / 128, 4), 256, SMEM_HID>>>(l1_b);

    k_l2_mma<<<dim3(BATCH / 128, EM / 128), 256>>>(l2_b, out);
    k_norm<<<BATCH, 256>>>(out);
}

// round 14
// speedup vs baseline: 1.1390x; 1.0069x over previous
#include <cuda_runtime.h>
#include <cuda_fp16.h>
#include <cstdint>

#define BATCH 16384
#define NK 100        // TENSOR_DIM
#define D 200         // 2*TENSOR_DIM
#define H1 512        // EMBED_SIZE/2
#define EM 1024       // EMBED_SIZE
#define WD 300        // WORD_DIM

#define PREAL 20400   // real quadratic pair count
#define PLIN  20600   // + 200 linear (term2) pairs
#define PPAD  20608   // padded to 32 (20600 = cl_b pair, rest zero)
#define NGROUP 5152   // PPAD / 4
#define NC32 644      // PPAD / 32
#define NCC  322      // chunk pairs
#define SPB_CHUNK 7680   // 120 n-rows * 32 p * 2B (global layout)
#define SPC 6656         // 104 n-rows * 64B (compact smem chunk)
#define T1_STR 104       // term1 row stride (tf32 bits, lrelu pre-applied)

// ---------------- scratch (device globals; no allocation) ----------------
__device__ float g_catT[D * BATCH];               // cat transposed [i][b]
__device__ unsigned char g_SpB[NC32 * SPB_CHUNK]; // Sp fp16, swizzled [c][n][p]
__device__ int2  g_groups[NGROUP];                // (j, i0) per 4-pair group
__device__ uint16_t g_gpk[NGROUP];                // packed (i0<<8)|j
__device__ float g_pdWT[WD * NK];
__device__ float g_l1WT[104 * H1];                // [k][m], rows 100..103 zero
__device__ unsigned char g_l2Wh[EM * H1 * 2];     // l2_W fp16 [e][k]
__device__ float g_term1[BATCH * T1_STR];         // lrelu(term1+term2+b), tf32 bits
__device__ uint32_t g_hu[BATCH * 256];            // h as packed half2 [b][256]

__device__ __forceinline__ float lrelu(float x) { return x >= 0.f ? x : 0.1f * x; }

__device__ __forceinline__ uint32_t smem_u32(const void* p) {
    return (uint32_t)__cvta_generic_to_shared(p);
}
__device__ __forceinline__ uint32_t f2tf32(float x) {
    uint32_t r; asm("cvt.rna.tf32.f32 %0, %1;" : "=r"(r) : "f"(x)); return r;
}
__device__ __forceinline__ uint32_t pack_h2(float lo, float hi) {
    __half2 h = __floats2half2_rn(lo, hi);
    return *(uint32_t*)&h;
}
#define CP_ASYNC16(dst, src) \
    asm volatile("cp.async.cg.shared.global [%0], [%1], 16;" :: "r"(dst), "l"(src) : "memory")
#define CP_COMMIT() asm volatile("cp.async.commit_group;" ::: "memory")

__device__ __forceinline__ void mma_tf32(float* d, const uint32_t* a,
                                         uint32_t b0, uint32_t b1) {
    asm volatile(
        "mma.sync.aligned.m16n8k8.row.col.f32.tf32.tf32.f32 "
        "{%0,%1,%2,%3}, {%4,%5,%6,%7}, {%8,%9}, {%0,%1,%2,%3};"
        : "+f"(d[0]), "+f"(d[1]), "+f"(d[2]), "+f"(d[3])
        : "r"(a[0]), "r"(a[1]), "r"(a[2]), "r"(a[3]), "r"(b0), "r"(b1));
}
__device__ __forceinline__ void mma_f16(float* d, const uint32_t* a,
                                        uint32_t b0, uint32_t b1) {
    asm volatile(
        "mma.sync.aligned.m16n8k16.row.col.f32.f16.f16.f32 "
        "{%0,%1,%2,%3}, {%4,%5,%6,%7}, {%8,%9}, {%0,%1,%2,%3};"
        : "+f"(d[0]), "+f"(d[1]), "+f"(d[2]), "+f"(d[3])
        : "r"(a[0]), "r"(a[1]), "r"(a[2]), "r"(a[3]), "r"(b0), "r"(b1));
}

// ================= fused prep 1: groups + small transposes + l2 half =======
__global__ void __launch_bounds__(256) k_pre1(const float* __restrict__ pd_W,
                                              const float* __restrict__ l1_W,
                                              const float* __restrict__ l2_W) {
    int bid = blockIdx.x;
    int tid = threadIdx.x;
    if (bid == 0) {
        int j = tid;
        if (j < 200) {
            int q = j >> 2, r = j & 3;
            int S = 2 * q * (q - 1) + r * q;
            int gbase = 50 * j - S;
            int i0 = j & ~3;
            int ng = (200 - i0) >> 2;
            for (int g = 0; g < ng; ++g) {
                int ii = i0 + 4 * g;
                g_groups[gbase + g] = make_int2(j, ii);
                g_gpk[gbase + g] = (uint16_t)((ii << 8) | j);
            }
        }
        int idx = j - 200;
        if (idx >= 0 && idx < 50) {
            g_groups[5100 + idx] = make_int2(200, idx * 4);
            g_gpk[5100 + idx] = (uint16_t)(((idx * 4) << 8) | 200);
        }
        if (idx == 50) { g_groups[5150] = make_int2(200, 200);
                         g_gpk[5150] = (uint16_t)((200 << 8) | 200); }
        if (idx == 51) { g_groups[5151] = make_int2(200, 204);
                         g_gpk[5151] = (uint16_t)((204 << 8) | 200); }
    } else if (bid <= 128) {
        int stride = 128 * 256;
        int t0 = (bid - 1) * 256 + tid;
        for (int l = t0; l < WD * NK; l += stride) {
            int c = l / NK, k = l - c * NK;
            g_pdWT[l] = pd_W[k * WD + c];
        }
        for (int l = t0; l < NK * H1; l += stride) {
            int k = l / H1, m = l - k * H1;
            g_l1WT[l] = l1_W[m * NK + k];
        }
    } else {
        int idx = (bid - 129) * 256 + tid;       // e*512 + k
        ((__half*)g_l2Wh)[idx] = __float2half_rn(l2_W[idx]);
    }
}

// ================= fused prep 2: Sp pack + cat (embedding+projdown) ========
__global__ void __launch_bounds__(256) k_pre2(const float* __restrict__ T,
                                              const float* __restrict__ clW,
                                              const float* __restrict__ clb,
                                              const int* __restrict__ x,
                                              const float* __restrict__ embed_W,
                                              const float* __restrict__ pd_b) {
    __shared__ float e_s[16][WD + 4];
    __shared__ float o_s[NK][17];
    __shared__ int   xs[16];
    int bid = blockIdx.x;
    int t = threadIdx.x;

    if (bid < NC32) {
        // ---- Sp pack ----
        int c = bid;
        unsigned char* base = g_SpB + (size_t)c * SPB_CHUNK;
        for (int e = t; e < 3840; e += 256) {
            int n = e >> 5, pl = e & 31;
            int p = c * 32 + pl;
            float v = 0.f;
            if (n < NK) {
                if (p < PREAL) {
                    int2 gi = g_groups[p >> 2];
                    int i = gi.y + (p & 3), j = gi.x;
                    if (i > j)       v = T[(n * D + i) * D + j] + T[(n * D + j) * D + i];
                    else if (i == j) v = T[(n * D + i) * D + i];
                } else if (p < PLIN) {
                    v = clW[n * D + (p - PREAL)];
                } else if (p == PLIN) {
                    v = clb[n];
                }
            }
            int w = pl >> 1;
            int sg = ((n >> 1) & 3) << 2;
            int off = n * 64 + ((w ^ sg) << 2) + (pl & 1) * 2;
            *(__half*)(base + off) = __float2half_rn(v);
        }
        return;
    }

    // ---- cat ----
    int g = bid - NC32;
    int row0 = g * 16;
    int slot = row0 / BATCH;
    int bbase = row0 - slot * BATCH;
    if (t < 16) xs[t] = x[(bbase + t) * 2 + slot];
    __syncthreads();
    for (int l = t; l < 16 * WD; l += 256) {
        int r = l / WD, c = l - r * WD;
        e_s[r][c] = embed_W[(size_t)xs[r] * WD + c];
    }
    __syncthreads();
    int k  = t & 127;
    int rt = t >> 7;
    if (k < NK) {
        float acc[8];
#pragma unroll
        for (int q = 0; q < 8; ++q) acc[q] = 0.f;
        for (int c4 = 0; c4 < WD; c4 += 4) {
            float w0 = g_pdWT[(c4 + 0) * NK + k];
            float w1 = g_pdWT[(c4 + 1) * NK + k];
            float w2 = g_pdWT[(c4 + 2) * NK + k];
            float w3 = g_pdWT[(c4 + 3) * NK + k];
#pragma unroll
            for (int q = 0; q < 8; ++q) {
                float4 e = *(const float4*)&e_s[rt + 2 * q][c4];
                acc[q] += e.x * w0 + e.y * w1 + e.z * w2 + e.w * w3;
            }
        }
        float bk = pd_b[k];
#pragma unroll
        for (int q = 0; q < 8; ++q)
            o_s[k][rt + 2 * q] = lrelu(acc[q] + bk);
    }
    __syncthreads();
    for (int l = t; l < NK * 16; l += 256) {
        int kk = l >> 4, col = l & 15;
        g_catT[(slot * NK + kk) * BATCH + bbase + col] = o_s[kk][col];
    }
}

// ---------------- main: term1(+term2+bias) via mma.sync fp16 ----------------
// CTA: 64 b x 104 n, 4 warps, 2 CTAs/SM. 64 pairs (2 chunks) per iteration.
// A-fragments for ALL 4 k16-steps generated up front (batched LDS latency),
// then the 52-HMMA stream runs uninterrupted.
#define CAT_STRIDE 228                          // words
#define SP_OFF   58368                          // 64 * 228 * 4
#define GRP_OFF  (SP_OFF + 2 * 2 * SPC)         // 84992
#define SMEM_MAIN (GRP_OFF + NGROUP * 2)        // 95296
#define BLOAD2 832                              // 2 chunks * 416 x 16B

__global__ void __launch_bounds__(128, 2) k_main_mma() {
    extern __shared__ char smem[];
    float* cat = (float*)smem;
    uint16_t* grp = (uint16_t*)(smem + GRP_OFF);
    uint32_t sb = smem_u32(smem);
    int tid = threadIdx.x, lane = tid & 31, wid = tid >> 5;
    int b0 = blockIdx.x * 64;

    // prologue: kick off pair 0 load into slot 0
    {
        const char* src = (const char*)g_SpB;
        for (int i = tid; i < BLOAD2; i += 128) {
            int ch = i / 416, off = i - ch * 416;
            CP_ASYNC16(sb + SP_OFF + ch * SPC + off * 16,
                       src + (size_t)ch * SPB_CHUNK + off * 16);
        }
        CP_COMMIT();
    }
    for (int l = tid; l < NGROUP / 2; l += 128)
        ((uint32_t*)grp)[l] = ((const uint32_t*)g_gpk)[l];
    for (int l = tid; l < D * 64; l += 128) {
        int i = l >> 6, b = l & 63;
        cat[b * CAT_STRIDE + i] = g_catT[i * BATCH + b0 + b];
    }
    if (tid < 64) {   // ones column + zero pad (slots 200..207)
        float* r = cat + tid * CAT_STRIDE;
        r[200] = 1.f;
#pragma unroll
        for (int s = 201; s < 208; ++s) r[s] = 0.f;
    }

    int gid = lane >> 2;      // 0..7
    int tc  = lane & 3;       // 0..3
    int R0 = wid * 16;
    int rA = R0 + gid;
    int oa = (tc & 1) * 2;    // i offset within group
    int gsel = tc >> 1;       // which of 2 sub-groups
    // B word offsets (conflict-free via block swizzle)
    int sgB = ((gid >> 1) & 3) << 2;
    int ob[2][2];
#pragma unroll
    for (int s = 0; s < 2; ++s) {
        ob[s][0] = gid * 16 + ((s * 8 + tc) ^ sgB);
        ob[s][1] = gid * 16 + ((s * 8 + tc + 4) ^ sgB);
    }

    float acc[13][4];
#pragma unroll
    for (int t = 0; t < 13; ++t)
#pragma unroll
        for (int q = 0; q < 4; ++q) acc[t][q] = 0.f;

    const float* r0 = cat + rA * CAT_STRIDE;
    const float* r1 = r0 + 8 * CAT_STRIDE;

    for (int cc = 0; cc < NCC; ++cc) {
        int slot = cc & 1;
        asm volatile("cp.async.wait_group 0;" ::: "memory");
        __syncthreads();   // pair cc visible; everyone done with other slot
        if (cc + 1 < NCC) {
            const char* src = (const char*)g_SpB + (size_t)(cc + 1) * 2 * SPB_CHUNK;
            uint32_t dst = sb + SP_OFF + (slot ^ 1) * 2 * SPC;
            for (int i = tid; i < BLOAD2; i += 128) {
                int ch = i / 416, off = i - ch * 416;
                CP_ASYNC16(dst + ch * SPC + off * 16,
                           src + (size_t)ch * SPB_CHUNK + off * 16);
            }
            CP_COMMIT();
        }

        // ---- batched A-gen: all 4 k16 steps of this 64-pair iteration ----
        uint32_t afr[4][4];
        int gb = cc * 16;
#pragma unroll
        for (int s4 = 0; s4 < 4; ++s4) {       // s4 = chunk*2 + ks
            int gbase = gb + (s4 >> 1) * 8 + (s4 & 1) * 4;
            int ga  = grp[gbase + gsel];
            int gb_ = grp[gbase + 2 + gsel];
            int ja = ga & 255,  ia = ga >> 8;
            int jb = gb_ & 255, ib = gb_ >> 8;
            float  ja0 = r0[ja], ja1 = r1[ja];
            float  jb0 = r0[jb], jb1 = r1[jb];
            float2 ia0 = *(const float2*)&r0[ia + oa];
            float2 ia1 = *(const float2*)&r1[ia + oa];
            float2 ib0 = *(const float2*)&r0[ib + oa];
            float2 ib1 = *(const float2*)&r1[ib + oa];
            afr[s4][0] = pack_h2(ia0.x * ja0, ia0.y * ja0);
            afr[s4][1] = pack_h2(ia1.x * ja1, ia1.y * ja1);
            afr[s4][2] = pack_h2(ib0.x * jb0, ib0.y * jb0);
            afr[s4][3] = pack_h2(ib1.x * jb1, ib1.y * jb1);
        }

        // ---- uninterrupted HMMA stream over both chunks ----
#pragma unroll
        for (int k = 0; k < 2; ++k) {
            const uint32_t* spu =
                (const uint32_t*)(smem + SP_OFF + slot * 2 * SPC + k * SPC);
#pragma unroll
            for (int ks = 0; ks < 2; ++ks) {
                int o0 = ob[ks][0], o1 = ob[ks][1];
                const uint32_t* a = afr[k * 2 + ks];
#pragma unroll
                for (int t = 0; t < 13; ++t) {
                    uint32_t bb0 = spu[o0 + t * 128];
                    uint32_t bb1 = spu[o1 + t * 128];
                    mma_f16(acc[t], a, bb0, bb1);
                }
            }
        }
    }

    // epilogue: write lrelu(term1) as tf32 bits (cols < 100; 100..103 stay 0)
    int cb = 2 * tc;
    int r = b0 + R0 + gid;
#pragma unroll
    for (int t = 0; t < 13; ++t) {
        int n0 = cb + t * 8;
        if (n0 < NK) {
            *(float2*)&g_term1[(size_t)r * T1_STR + n0] = make_float2(
                __uint_as_float(f2tf32(lrelu(acc[t][0]))),
                __uint_as_float(f2tf32(lrelu(acc[t][1]))));
            *(float2*)&g_term1[(size_t)(r + 8) * T1_STR + n0] = make_float2(
                __uint_as_float(f2tf32(lrelu(acc[t][2]))),
                __uint_as_float(f2tf32(lrelu(acc[t][3]))));
        }
    }
}

// ---------------- hidden: h = lrelu(A @ l1W^T + b), tf32 mma ----------------
// A loaded ONCE per 128-b tile; 4 m-blocks streamed with B double-buffer.
#define HA_STR 108
#define HB_STR 136
#define HB_OFF 55296
#define HB_SZ  (104 * HB_STR * 4)               // 56576 per buffer
#define SMEM_HID (HB_OFF + 2 * HB_SZ)           // 168448

__global__ void __launch_bounds__(256) k_hid(const float* __restrict__ l1_b) {
    extern __shared__ char sm2[];
    float*    As = (float*)sm2;
    int tid = threadIdx.x, lane = tid & 31, wid = tid >> 5;
    int b0 = blockIdx.x * 128;

    // A: 128 rows x 26 float4 chunks + B block 0 — one commit group
    for (int i = tid; i < 3328; i += 256) {
        int r = i / 26, q = i - r * 26;
        CP_ASYNC16(smem_u32(As + r * HA_STR) + q * 16,
                   (const char*)(g_term1 + (size_t)(b0 + r) * T1_STR) + q * 16);
    }
    {
        uint32_t* Bs = (uint32_t*)(sm2 + HB_OFF);
        for (int i = tid; i < 3328; i += 256) {
            int r = i >> 5, q = i & 31;
            CP_ASYNC16(smem_u32(&Bs[r * HB_STR + q * 4]),
                       (const char*)(g_l1WT + r * H1 + q * 4));
        }
    }
    CP_COMMIT();

    int rw = wid & 3, cw = wid >> 2;
    int R0 = rw * 32;
    int ic = lane & 3;

    for (int mb = 0; mb < 4; ++mb) {
        int buf = mb & 1;
        __syncthreads();     // everyone done with buffer buf (GEMM mb-2)
        if (mb < 3) {
            uint32_t* Bn = (uint32_t*)(sm2 + HB_OFF + ((mb + 1) & 1) * HB_SZ);
            for (int i = tid; i < 3328; i += 256) {
                int r = i >> 5, q = i & 31;
                CP_ASYNC16(smem_u32(&Bn[r * HB_STR + q * 4]),
                           (const char*)(g_l1WT + r * H1 + (mb + 1) * 128 + q * 4));
            }
            CP_COMMIT();
            asm volatile("cp.async.wait_group 1;" ::: "memory");
        } else {
            asm volatile("cp.async.wait_group 0;" ::: "memory");
        }
        __syncthreads();     // A (mb==0) + B[mb] visible

        const uint32_t* Bs = (const uint32_t*)(sm2 + HB_OFF + buf * HB_SZ);
        float acc[2][8][4];
#pragma unroll
        for (int f = 0; f < 2; ++f)
#pragma unroll
            for (int t = 0; t < 8; ++t)
#pragma unroll
                for (int q = 0; q < 4; ++q) acc[f][t][q] = 0.f;

#pragma unroll
        for (int kk = 0; kk < 13; ++kk) {
            uint32_t af[2][4];
#pragma unroll
            for (int f = 0; f < 2; ++f) {
                const uint32_t* hp = (const uint32_t*)As +
                    (R0 + f * 16 + (lane >> 2)) * HA_STR + kk * 8 + ic;
                af[f][0] = hp[0];
                af[f][1] = hp[8 * HA_STR];
                af[f][2] = hp[4];
                af[f][3] = hp[8 * HA_STR + 4];
            }
            const uint32_t* wp = &Bs[(kk * 8 + ic) * HB_STR + cw * 64 + (lane >> 2)];
#pragma unroll
            for (int t = 0; t < 8; ++t) {
                uint32_t bb0 = wp[t * 8];
                uint32_t bb1 = wp[4 * HB_STR + t * 8];
                mma_tf32(acc[0][t], af[0], bb0, bb1);
                mma_tf32(acc[1][t], af[1], bb0, bb1);
            }
        }

#pragma unroll
        for (int t = 0; t < 8; ++t) {
            int m = mb * 128 + cw * 64 + t * 8 + 2 * ic;
            float bm0 = l1_b[m], bm1 = l1_b[m + 1];
#pragma unroll
            for (int f = 0; f < 2; ++f) {
                int r = b0 + R0 + f * 16 + (lane >> 2);
                g_hu[(size_t)r * 256 + (m >> 1)] =
                    pack_h2(lrelu(acc[f][t][0] + bm0), lrelu(acc[f][t][1] + bm1));
                g_hu[(size_t)(r + 8) * 256 + (m >> 1)] =
                    pack_h2(lrelu(acc[f][t][2] + bm0), lrelu(acc[f][t][3] + bm1));
            }
        }
    }
}

// ---------------- l2 GEMM via mma.sync fp16 ----------------
#define L2_STR 12   // words per row (8 used + 4 pad)
__global__ void __launch_bounds__(256) k_l2_mma(const float* __restrict__ l2_b,
                                                float* __restrict__ out) {
    __shared__ uint32_t hs[2][128 * L2_STR];
    __shared__ uint32_t ws[2][128 * L2_STR];
    int tid = threadIdx.x, lane = tid & 31, wid = tid >> 5;
    int b0 = blockIdx.x * 128, e0 = blockIdx.y * 128;
    int rw = wid & 3, cw = wid >> 2;
    int R0 = rw * 32;
    int gid = lane >> 2, tc = lane & 3;

    float acc[2][8][4];
#pragma unroll
    for (int f = 0; f < 2; ++f)
#pragma unroll
        for (int t = 0; t < 8; ++t)
#pragma unroll
            for (int q = 0; q < 4; ++q) acc[f][t][q] = 0.f;

    auto issue = [&](int kt, int s) {
        {
            int r = tid >> 1, q = tid & 1;
            const char* src = (const char*)(g_hu + (size_t)(b0 + r) * 256 + kt * 8) + q * 16;
            CP_ASYNC16(smem_u32(&hs[s][r * L2_STR]) + q * 16, src);
        }
        {
            int r = tid >> 1, q = tid & 1;
            const char* src = (const char*)g_l2Wh + ((size_t)(e0 + r) * 512 + kt * 16) * 2 + q * 16;
            CP_ASYNC16(smem_u32(&ws[s][r * L2_STR]) + q * 16, src);
        }
        CP_COMMIT();
    };
    issue(0, 0);

    for (int kt = 0; kt < 32; ++kt) {
        int s = kt & 1;
        if (kt + 1 < 32) {
            issue(kt + 1, s ^ 1);
            asm volatile("cp.async.wait_group 1;" ::: "memory");
        } else {
            asm volatile("cp.async.wait_group 0;" ::: "memory");
        }
        __syncthreads();

        uint32_t af[2][4];
#pragma unroll
        for (int f = 0; f < 2; ++f) {
            const uint32_t* hp = &hs[s][(R0 + f * 16 + gid) * L2_STR];
            af[f][0] = hp[tc];
            af[f][1] = hp[8 * L2_STR + tc];
            af[f][2] = hp[tc + 4];
            af[f][3] = hp[8 * L2_STR + tc + 4];
        }
        const uint32_t* wp = &ws[s][(cw * 64 + gid) * L2_STR];
#pragma unroll
        for (int t = 0; t < 8; ++t) {
            uint32_t bb0 = wp[t * 8 * L2_STR + tc];
            uint32_t bb1 = wp[t * 8 * L2_STR + tc + 4];
            mma_f16(acc[0][t], af[0], bb0, bb1);
            mma_f16(acc[1][t], af[1], bb0, bb1);
        }
        __syncthreads();
    }

#pragma unroll
    for (int t = 0; t < 8; ++t) {
        int e = e0 + cw * 64 + t * 8 + 2 * tc;
        float be0 = l2_b[e], be1 = l2_b[e + 1];
#pragma unroll
        for (int f = 0; f < 2; ++f) {
            int r = b0 + R0 + f * 16 + gid;
            *(float2*)&out[(size_t)r * EM + e] =
                make_float2(acc[f][t][0] + be0, acc[f][t][1] + be1);
            *(float2*)&out[(size_t)(r + 8) * EM + e] =
                make_float2(acc[f][t][2] + be0, acc[f][t][3] + be1);
        }
    }
}

// ---------------- row-wise L2 normalization ----------------
__global__ void __launch_bounds__(256) k_norm(float* __restrict__ out) {
    __shared__ float wsum[8];
    int b = blockIdx.x;
    int t = threadIdx.x;
    float4* row = (float4*)(out + (size_t)b * EM);
    float4 v = row[t];
    float s = v.x * v.x + v.y * v.y + v.z * v.z + v.w * v.w;
#pragma unroll
    for (int off = 16; off > 0; off >>= 1)
        s += __shfl_xor_sync(0xffffffffu, s, off);
    if ((t & 31) == 0) wsum[t >> 5] = s;
    __syncthreads();
    float tot = wsum[0] + wsum[1] + wsum[2] + wsum[3] +
                wsum[4] + wsum[5] + wsum[6] + wsum[7];
    float inv = rsqrtf(tot);
    row[t] = make_float4(v.x * inv, v.y * inv, v.z * inv, v.w * inv);
}

// ---------------- launch ----------------
extern "C" void kernel_launch(void* const* d_in, const int* in_sizes, int n_in,
                              void* d_out, int out_size) {
    const int*   x       = (const int*)d_in[0];
    const float* embed_W = (const float*)d_in[2];
    const float* pd_W    = (const float*)d_in[3];
    const float* pd_b    = (const float*)d_in[4];
    const float* comp_T  = (const float*)d_in[5];
    const float* cl_W    = (const float*)d_in[6];
    const float* cl_b    = (const float*)d_in[7];
    const float* l1_W    = (const float*)d_in[8];
    const float* l1_b    = (const float*)d_in[9];
    const float* l2_W    = (const float*)d_in[10];
    const float* l2_b    = (const float*)d_in[11];
    float* out = (float*)d_out;

    k_pre1<<<1 + 128 + (H1 * EM) / 256, 256>>>(pd_W, l1_W, l2_W);
    k_pre2<<<NC32 + (2 * BATCH) / 16, 256>>>(comp_T, cl_W, cl_b,
                                             x, embed_W, pd_b);

    cudaFuncSetAttribute(k_main_mma, cudaFuncAttributeMaxDynamicSharedMemorySize,
                         SMEM_MAIN);
    k_main_mma<<<BATCH / 64, 128, SMEM_MAIN>>>();

    cudaFuncSetAttribute(k_hid, cudaFuncAttributeMaxDynamicSharedMemorySize,
                         SMEM_HID);
    k_hid<<<BATCH / 128, 256, SMEM_HID>>>(l1_b);

    k_l2_mma<<<dim3(BATCH / 128, EM / 128), 256>>>(l2_b, out);
    k_norm<<<BATCH, 256>>>(out);
}